// round 14
// baseline (speedup 1.0000x reference)
#include <cuda_runtime.h>
#include <cuda_bf16.h>
#include <cstdint>

#define NB 8
#define SS 1024
#define DD 64
#define HID 512
#define NTOK (NB*SS)          // 8192
#define EPSV 1e-6f

// ---------------- device scratch (no allocation allowed) ----------------
__device__ float g_Q[NTOK*DD];
__device__ float g_K[NTOK*DD];
__device__ float g_V[NTOK*DD];
__device__ float g_gate[NTOK*2];
__device__ float g_rs[6*NTOK];           // rowsums: slots 1..5 = P,Qm,A2,P2,Q2
__device__ float g_frs[2*NTOK];          // rowsums of fused matrices (atomic)
__device__ float g_H[2*NTOK*DD];         // hop outputs (pre-norm, atomic)
__device__ float g_A [(size_t)NB*SS*SS]; // softmax attention
__device__ float g_P [(size_t)NB*SS*SS]; // A A^T
__device__ float g_Qm[(size_t)NB*SS*SS]; // A^T A
__device__ float g_A2[(size_t)NB*SS*SS]; // A A
__device__ float g_P2[(size_t)NB*SS*SS]; // P P
__device__ float g_Q2[(size_t)NB*SS*SS]; // Qm Qm
__device__ float g_hopvT[2*(size_t)NB*DD*SS]; // hopv transposed, k-major, fp32
// bf16 GEMM operands
__device__ __nv_bfloat16 g_Ah [(size_t)NB*SS*SS];
__device__ __nv_bfloat16 g_Th [(size_t)NB*SS*SS];
__device__ __nv_bfloat16 g_Ph [(size_t)NB*SS*SS];
__device__ __nv_bfloat16 g_Qmh[(size_t)NB*SS*SS];

__device__ __forceinline__ float* matsel(int s) {
    switch (s) {
        case 0: return g_A;
        case 1: return g_P;
        case 2: return g_Qm;
        case 3: return g_A2;
        case 4: return g_P2;
        default: return g_Q2;
    }
}
__device__ __forceinline__ __nv_bfloat16* hmatsel(int s) {
    switch (s) {
        case 0: return g_Ah;
        case 1: return g_Th;
        case 2: return g_Ph;
        default: return g_Qmh;
    }
}

__device__ __forceinline__ float warp_max(float v) {
    #pragma unroll
    for (int o = 16; o > 0; o >>= 1) v = fmaxf(v, __shfl_xor_sync(0xffffffffu, v, o));
    return v;
}
__device__ __forceinline__ float warp_sum(float v) {
    #pragma unroll
    for (int o = 16; o > 0; o >>= 1) v += __shfl_xor_sync(0xffffffffu, v, o);
    return v;
}

// ---------------- 0) zero g_rs + g_frs + g_H ----------------
#define ZTOT ((6*NTOK + 2*NTOK + 2*NTOK*DD)/4)
__global__ void zero_kernel()
{
    int gid = blockIdx.x*256 + threadIdx.x;   // float4 index
    if (gid >= ZTOT) return;
    if (gid < 6*NTOK/4)
        ((float4*)g_rs)[gid] = make_float4(0.f,0.f,0.f,0.f);
    else if (gid < (6*NTOK + 2*NTOK)/4)
        ((float4*)g_frs)[gid - 6*NTOK/4] = make_float4(0.f,0.f,0.f,0.f);
    else
        ((float4*)g_H)[gid - (6*NTOK + 2*NTOK)/4] = make_float4(0.f,0.f,0.f,0.f);
}
#define ZERO_BLOCKS ((ZTOT + 255)/256)

// ---------------- 1) QKV + gate-logit projection ----------------
#define TOK_PB 16
__global__ __launch_bounds__(256) void proj_kernel(
    const float* __restrict__ x, const float* __restrict__ Wq,
    const float* __restrict__ Wk, const float* __restrict__ Wv,
    const float* __restrict__ gW)
{
    __shared__ float xs[TOK_PB*HID];
    int tb = blockIdx.x * TOK_PB;
    int tid = threadIdx.x;
    const float4* xg = (const float4*)(x + (size_t)tb*HID);
    float4* xs4 = (float4*)xs;
    #pragma unroll
    for (int i = tid; i < TOK_PB*HID/4; i += 256) xs4[i] = xg[i];
    __syncthreads();

    for (int o = tid; o < TOK_PB*194; o += 256) {
        int tok = o / 194, ch = o % 194;
        const float* w;
        if (ch < 64)       w = Wq + ch*HID;
        else if (ch < 128) w = Wk + (ch-64)*HID;
        else if (ch < 192) w = Wv + (ch-128)*HID;
        else               w = gW + (ch-192)*HID;
        const float4* w4  = (const float4*)w;
        const float4* xv4 = (const float4*)(xs + tok*HID);
        float acc = 0.f;
        #pragma unroll 8
        for (int k = 0; k < HID/4; k++) {
            float4 a = xv4[k];
            float4 b = __ldg(&w4[k]);
            acc += a.x*b.x + a.y*b.y + a.z*b.z + a.w*b.w;
        }
        size_t gt = tb + tok;
        if (ch < 64)       g_Q[gt*DD + ch]        = acc;
        else if (ch < 128) g_K[gt*DD + (ch-64)]   = acc;
        else if (ch < 192) g_V[gt*DD + (ch-128)]  = acc;
        else               g_gate[gt*2 + (ch-192)] = acc;
    }
}

// ---------------- 2) RoPE in place on Q,K ----------------
__global__ void rope_kernel()
{
    int gid = blockIdx.x*256 + threadIdx.x;
    if (gid >= NTOK*32) return;
    int tok = gid >> 5, j = gid & 31;
    int s = tok & (SS-1);
    float invf = (float)exp(-log(10000.0) * (double)j / 32.0);
    float ang = (float)s * invf;
    float sn, cs;
    sincosf(ang, &sn, &cs);
    size_t base = (size_t)tok * DD;
    float q0 = g_Q[base+j], q1 = g_Q[base+j+32];
    g_Q[base+j]    = q0*cs - q1*sn;
    g_Q[base+j+32] = q1*cs + q0*sn;
    float k0 = g_K[base+j], k1 = g_K[base+j+32];
    g_K[base+j]    = k0*cs - k1*sn;
    g_K[base+j+32] = k1*cs + k0*sn;
}

// ---------------- 3) hopvT (coalesced, e-split) ; gate softmax ----------------
__global__ __launch_bounds__(256) void hopv_gate_kernel(
    const float* __restrict__ hopW, const float* __restrict__ gateb)
{
    __shared__ float vs[64][65];
    int t0tok = blockIdx.x * 64;
    int eq = blockIdx.y;                       // e quarter 0..3
    int b = t0tok >> 10, s0 = t0tok & (SS-1);
    int tid = threadIdx.x;

    #pragma unroll
    for (int i = tid; i < 64*16; i += 256) {   // float4 granules
        int tokL = i >> 4;
        int d4 = (i & 15) * 4;
        float4 v = *(const float4*)(g_V + (size_t)(t0tok + tokL)*DD + d4);
        vs[tokL][d4] = v.x; vs[tokL][d4+1] = v.y;
        vs[tokL][d4+2] = v.z; vs[tokL][d4+3] = v.w;
    }
    __syncthreads();

    int tokL = tid & 63;
    int e0 = eq*16 + (tid >> 6);               // 4 e per block-thread-group
    int s = s0 + tokL;
    #pragma unroll 4
    for (int e = e0; e < eq*16 + 16; e += 4) {
        const float* w0 = hopW + e*DD;
        const float* w1 = hopW + DD*DD + e*DD;
        float a0 = 0.f, a1 = 0.f;
        #pragma unroll
        for (int d = 0; d < DD; d++) {
            float v = vs[tokL][d];
            a0 += v * __ldg(&w0[d]);
            a1 += v * __ldg(&w1[d]);
        }
        g_hopvT[((size_t)b*DD + e)*SS + s] = a0;
        g_hopvT[((size_t)(NB + b)*DD + e)*SS + s] = a1;
    }

    if (eq == 0 && tid < 64) {
        int tok = t0tok + tid;
        float l0 = g_gate[tok*2]   + __ldg(&gateb[0]);
        float l1 = g_gate[tok*2+1] + __ldg(&gateb[1]);
        float m = fmaxf(l0, l1);
        float e0v = __expf(l0-m), e1v = __expf(l1-m);
        float inv = 1.f/(e0v+e1v);
        g_gate[tok*2]   = e0v*inv;
        g_gate[tok*2+1] = e1v*inv;
    }
}

// ---------------- 4) scores ----------------
__global__ __launch_bounds__(256) void scores_kernel(
    const float* __restrict__ bias_table, const int* __restrict__ rel_idx,
    const float* __restrict__ temperature)
{
    __shared__ float qs[64][65];
    __shared__ float ks[64][65];
    int b = blockIdx.z;
    int s0 = blockIdx.y * 64, t0 = blockIdx.x * 64;
    int tid = threadIdx.x;
    const float* Qb = g_Q + ((size_t)b*SS + s0)*DD;
    const float* Kb = g_K + ((size_t)b*SS + t0)*DD;
    #pragma unroll
    for (int e = tid; e < 64*64; e += 256) {
        qs[e>>6][e&63] = Qb[e];
        ks[e>>6][e&63] = Kb[e];
    }
    __syncthreads();
    int ty = tid >> 4, tx = tid & 15;
    float c[4][4];
    #pragma unroll
    for (int i=0;i<4;i++) { c[i][0]=0;c[i][1]=0;c[i][2]=0;c[i][3]=0; }
    #pragma unroll 4
    for (int d = 0; d < 64; d++) {
        float rq[4], rk[4];
        #pragma unroll
        for (int i=0;i<4;i++) { rq[i] = qs[ty*4+i][d]; rk[i] = ks[tx*4+i][d]; }
        #pragma unroll
        for (int i=0;i<4;i++)
            #pragma unroll
            for (int j=0;j<4;j++) c[i][j] += rq[i]*rk[j];
    }
    float inv_t = 1.f / fmaxf(temperature[0], 0.1f);
    const float scale = 0.125f;
    float* Ab = g_A + (size_t)b*SS*SS;
    #pragma unroll
    for (int i = 0; i < 4; i++) {
        int s = s0 + ty*4 + i;
        int4 idx = *(const int4*)(rel_idx + (size_t)s*SS + t0 + tx*4);
        float4 out;
        out.x = (c[i][0]*scale + __ldg(&bias_table[idx.x])) * inv_t;
        out.y = (c[i][1]*scale + __ldg(&bias_table[idx.y])) * inv_t;
        out.z = (c[i][2]*scale + __ldg(&bias_table[idx.z])) * inv_t;
        out.w = (c[i][3]*scale + __ldg(&bias_table[idx.w])) * inv_t;
        *(float4*)(Ab + (size_t)s*SS + t0 + tx*4) = out;
    }
}

// ---------------- 5) row softmax in place on g_A (+ bf16 copy) ----------------
__global__ __launch_bounds__(256) void softmax_kernel()
{
    size_t row = blockIdx.x;
    float* Ar = g_A + row*SS;
    __nv_bfloat16* Ah = g_Ah + row*SS;
    int tid = threadIdx.x;
    int wid = tid >> 5, lane = tid & 31;
    __shared__ float sm[8];
    float4 v = ((float4*)Ar)[tid];
    float m = fmaxf(fmaxf(v.x, v.y), fmaxf(v.z, v.w));
    m = warp_max(m);
    if (lane == 0) sm[wid] = m;
    __syncthreads();
    if (wid == 0) {
        float t = (lane < 8) ? sm[lane] : -3.4e38f;
        t = warp_max(t);
        if (lane == 0) sm[0] = t;
    }
    __syncthreads();
    m = sm[0];
    __syncthreads();
    float e0 = __expf(v.x-m), e1 = __expf(v.y-m), e2 = __expf(v.z-m), e3 = __expf(v.w-m);
    float s = e0+e1+e2+e3;
    s = warp_sum(s);
    if (lane == 0) sm[wid] = s;
    __syncthreads();
    if (wid == 0) {
        float t = (lane < 8) ? sm[lane] : 0.f;
        t = warp_sum(t);
        if (lane == 0) sm[0] = t;
    }
    __syncthreads();
    float inv = 1.f / sm[0];
    float4 o = make_float4(e0*inv, e1*inv, e2*inv, e3*inv);
    ((float4*)Ar)[tid] = o;
    __nv_bfloat162 h0 = __floats2bfloat162_rn(o.x, o.y);
    __nv_bfloat162 h1 = __floats2bfloat162_rn(o.z, o.w);
    ((__nv_bfloat162*)Ah)[tid*2]   = h0;
    ((__nv_bfloat162*)Ah)[tid*2+1] = h1;
}

// ---------------- 5b) transpose: g_Th = (g_Ah)^T per batch (bf16 in/out) ----------------
__global__ __launch_bounds__(256) void transpose_kernel()
{
    __shared__ __nv_bfloat16 t[32][34];
    int b = blockIdx.z;
    int x0 = blockIdx.x*32, y0 = blockIdx.y*32;
    const __nv_bfloat16* Ab = g_Ah + (size_t)b*SS*SS;
    __nv_bfloat16* Tb = g_Th + (size_t)b*SS*SS;
    int tx = threadIdx.x & 31, ty = threadIdx.x >> 5;   // 32 x 8
    #pragma unroll
    for (int i = 0; i < 32; i += 8)
        t[ty+i][tx] = Ab[(size_t)(y0+ty+i)*SS + x0+tx];
    __syncthreads();
    #pragma unroll
    for (int i = 0; i < 32; i += 8)
        Tb[(size_t)(x0+ty+i)*SS + y0+tx] = t[tx][ty+i];
}

// ================= bf16 mma.sync batched NT GEMM (+rowsum epilogue) =================
__device__ __forceinline__ uint32_t s2u(const void* p) {
    uint32_t a;
    asm("{ .reg .u64 t; cvta.to.shared.u64 t, %1; cvt.u32.u64 %0, t; }" : "=r"(a) : "l"(p));
    return a;
}
#define SWZ(o) ((o) ^ (((o)>>3)&0x70))

__device__ __forceinline__ void cp16(uint32_t dst, const void* src) {
    asm volatile("cp.async.cg.shared.global [%0], [%1], 16;" :: "r"(dst), "l"(src));
}
__device__ __forceinline__ void cp_commit() { asm volatile("cp.async.commit_group;" ::: "memory"); }
#define CP_WAIT(n) asm volatile("cp.async.wait_group %0;" :: "n"(n) : "memory")

__device__ __forceinline__ void ldsm4(uint32_t* r, uint32_t addr) {
    asm volatile("ldmatrix.sync.aligned.m8n8.x4.shared.b16 {%0,%1,%2,%3}, [%4];"
        : "=r"(r[0]), "=r"(r[1]), "=r"(r[2]), "=r"(r[3]) : "r"(addr));
}
__device__ __forceinline__ void mma_bf16(float* c, const uint32_t* a,
                                         uint32_t b0, uint32_t b1) {
    asm volatile(
        "mma.sync.aligned.m16n8k16.row.col.f32.bf16.bf16.f32 "
        "{%0,%1,%2,%3},{%4,%5,%6,%7},{%8,%9},{%0,%1,%2,%3};"
        : "+f"(c[0]), "+f"(c[1]), "+f"(c[2]), "+f"(c[3])
        : "r"(a[0]), "r"(a[1]), "r"(a[2]), "r"(a[3]), "r"(b0), "r"(b1));
}

#define STG 3
#define CK 64                        // k per chunk (bf16): 128B per row
#define NCH (SS/CK)                  // 16
#define STAGE_BYTES 32768
#define GEMM_DSMEM (STG*STAGE_BYTES) // 98304

__global__ __launch_bounds__(256, 2)
void gemm_bf16_kernel(int asel, int bsel, int cfsel, int chsel, int tri)
{
    extern __shared__ __align__(16) char dsmem[];
    uint32_t sb = s2u(dsmem);
    int tid = threadIdx.x;
    int warp = tid >> 5, lane = tid & 31;

    size_t off = (size_t)blockIdx.z*SS*SS;
    const __nv_bfloat16* Ag = hmatsel(asel) + off;
    const __nv_bfloat16* Bg = hmatsel(bsel) + off;
    float* Cg = matsel(cfsel) + off;
    __nv_bfloat16* Chg = (chsel >= 0) ? hmatsel(chsel) + off : nullptr;

    int bi, bj;
    if (tri) {
        int t = blockIdx.x, i = 0;
        while (t >= 8 - i) { t -= 8 - i; i++; }
        bi = i; bj = i + t;
    } else {
        bi = blockIdx.x >> 3; bj = blockIdx.x & 7;
    }
    int m0 = bi*128, n0 = bj*128;
    bool same = (tri != 0) && (bi == bj) && (asel == bsel);
    uint32_t bBase = same ? 0u : 16384u;

    int wm = (warp >> 2)*64, wn = (warp & 3)*32;
    int rlane = (lane & 7) + ((lane >> 3) & 1)*8;
    int clane = (lane >> 4) & 1;

    float acc[4][4][4];
    #pragma unroll
    for (int i = 0; i < 4; i++)
        #pragma unroll
        for (int j = 0; j < 4; j++) {
            acc[i][j][0]=0; acc[i][j][1]=0; acc[i][j][2]=0; acc[i][j][3]=0;
        }

    auto load_chunk = [&](int c) {
        uint32_t stg = sb + (uint32_t)(c % STG) * STAGE_BYTES;
        int k0 = c * CK;
        #pragma unroll
        for (int it = 0; it < 8; it++) {
            int u = tid + it*256;
            int r = u >> 3;
            int ch = u & 7;
            if (r < 128) {
                const __nv_bfloat16* gsrc = Ag + (size_t)(m0 + r)*SS + k0 + ch*8;
                cp16(stg + SWZ((uint32_t)(r*128 + ch*16)), gsrc);
            } else if (!same) {
                const __nv_bfloat16* gsrc = Bg + (size_t)(n0 + (r-128))*SS + k0 + ch*8;
                cp16(stg + 16384u + SWZ((uint32_t)((r-128)*128 + ch*16)), gsrc);
            }
        }
    };

    for (int c = 0; c < STG-1; c++) { load_chunk(c); cp_commit(); }

    for (int c = 0; c < NCH; c++) {
        int lc = c + STG - 1;
        if (lc < NCH) load_chunk(lc);
        cp_commit();
        CP_WAIT(STG-1);
        __syncthreads();
        uint32_t stg = sb + (uint32_t)(c % STG) * STAGE_BYTES;
        #pragma unroll
        for (int ks = 0; ks < CK/16; ks++) {
            uint32_t af[4][4], bfr[2][4];
            int kch = ks*2 + clane;
            #pragma unroll
            for (int mi = 0; mi < 4; mi++) {
                int r = wm + mi*16 + rlane;
                ldsm4(af[mi], stg + SWZ((uint32_t)(r*128 + kch*16)));
            }
            #pragma unroll
            for (int nt = 0; nt < 2; nt++) {
                int r = wn + nt*16 + rlane;
                ldsm4(bfr[nt], stg + bBase + SWZ((uint32_t)(r*128 + kch*16)));
            }
            #pragma unroll
            for (int mi = 0; mi < 4; mi++)
                #pragma unroll
                for (int nj = 0; nj < 4; nj++) {
                    int nt = nj >> 1, sel = nj & 1;
                    mma_bf16(acc[mi][nj], af[mi], bfr[nt][sel], bfr[nt][sel+2]);
                }
        }
        __syncthreads();
    }

    int rr = lane >> 2, cc2 = (lane & 3)*2;
    #pragma unroll
    for (int mi = 0; mi < 4; mi++) {
        #pragma unroll
        for (int nj = 0; nj < 4; nj++) {
            int row = m0 + wm + mi*16 + rr;
            int col = n0 + wn + nj*8 + cc2;
            float2 v01 = make_float2(acc[mi][nj][0], acc[mi][nj][1]);
            float2 v23 = make_float2(acc[mi][nj][2], acc[mi][nj][3]);
            *(float2*)&Cg[(size_t)row*SS + col]     = v01;
            *(float2*)&Cg[(size_t)(row+8)*SS + col] = v23;
            if (Chg) {
                *(__nv_bfloat162*)&Chg[(size_t)row*SS + col] =
                    __floats2bfloat162_rn(v01.x, v01.y);
                *(__nv_bfloat162*)&Chg[(size_t)(row+8)*SS + col] =
                    __floats2bfloat162_rn(v23.x, v23.y);
            }
        }
    }

    // ---- rowsum epilogue: slot index == cfsel ----
    float* rs = g_rs + (size_t)cfsel*NTOK + (size_t)blockIdx.z*SS;
    #pragma unroll
    for (int mi = 0; mi < 4; mi++) {
        float r0 = 0.f, r1 = 0.f;
        #pragma unroll
        for (int nj = 0; nj < 4; nj++) {
            r0 += acc[mi][nj][0] + acc[mi][nj][1];
            r1 += acc[mi][nj][2] + acc[mi][nj][3];
        }
        r0 += __shfl_xor_sync(0xffffffffu, r0, 1);
        r0 += __shfl_xor_sync(0xffffffffu, r0, 2);
        r1 += __shfl_xor_sync(0xffffffffu, r1, 1);
        r1 += __shfl_xor_sync(0xffffffffu, r1, 2);
        if ((lane & 3) == 0) {
            int row = m0 + wm + mi*16 + rr;
            atomicAdd(&rs[row], r0);
            atomicAdd(&rs[row+8], r1);
        }
    }
    if (tri && bi != bj) {
        #pragma unroll
        for (int nj = 0; nj < 4; nj++) {
            float c0 = 0.f, c1 = 0.f;
            #pragma unroll
            for (int mi = 0; mi < 4; mi++) {
                c0 += acc[mi][nj][0] + acc[mi][nj][2];
                c1 += acc[mi][nj][1] + acc[mi][nj][3];
            }
            c0 += __shfl_xor_sync(0xffffffffu, c0, 4);
            c0 += __shfl_xor_sync(0xffffffffu, c0, 8);
            c0 += __shfl_xor_sync(0xffffffffu, c0, 16);
            c1 += __shfl_xor_sync(0xffffffffu, c1, 4);
            c1 += __shfl_xor_sync(0xffffffffu, c1, 8);
            c1 += __shfl_xor_sync(0xffffffffu, c1, 16);
            if (lane < 4) {
                int col = n0 + wn + nj*8 + cc2;
                atomicAdd(&rs[col], c0);
                atomicAdd(&rs[col+1], c1);
            }
        }
    }
}

// ---------------- 6b) mirror lower triangle of two symmetric matrices ----------------
__global__ __launch_bounds__(256) void mirror2_kernel(
    int m0sel, int h0sel, int m1sel, int h1sel)
{
    __shared__ float t[32][33];
    size_t off = (size_t)blockIdx.z*SS*SS;
    int which = blockIdx.y >> 4;
    int msel = which ? m1sel : m0sel;
    int hsel = which ? h1sel : h0sel;
    float* M = matsel(msel) + off;
    __nv_bfloat16* Mh = (hsel >= 0) ? hmatsel(hsel) + off : nullptr;

    int p = blockIdx.x, i = 0;
    while (p >= 7 - i) { p -= 7 - i; i++; }
    int j = i + 1 + p;
    int sub = blockIdx.y & 15;
    int y0 = i*128 + (sub >> 2)*32;
    int x0 = j*128 + (sub & 3)*32;
    int tx = threadIdx.x & 31, ty = threadIdx.x >> 5;
    #pragma unroll
    for (int k = 0; k < 32; k += 8)
        t[ty+k][tx] = M[(size_t)(y0+ty+k)*SS + x0+tx];
    __syncthreads();
    #pragma unroll
    for (int k = 0; k < 32; k += 8) {
        float v = t[tx][ty+k];
        size_t dst = (size_t)(x0+ty+k)*SS + y0+tx;
        M[dst] = v;
        if (Mh) Mh[dst] = __float2bfloat16(v);
    }
}

// ---------------- 8) fused F-compute + hop GEMM (TF32, split-K x4) ----------------
__device__ __forceinline__ float to_tf32(float x) {
    uint32_t u;
    asm("cvt.rna.tf32.f32 %0, %1;" : "=r"(u) : "f"(x));
    return __uint_as_float(u);
}
__device__ __forceinline__ void mma_tf32(float* c,
    uint32_t a0, uint32_t a1, uint32_t a2, uint32_t a3, uint32_t b0, uint32_t b1)
{
    asm volatile(
        "mma.sync.aligned.m16n8k8.row.col.f32.tf32.tf32.f32 "
        "{%0,%1,%2,%3},{%4,%5,%6,%7},{%8,%9},{%0,%1,%2,%3};"
        : "+f"(c[0]), "+f"(c[1]), "+f"(c[2]), "+f"(c[3])
        : "r"(a0), "r"(a1), "r"(a2), "r"(a3), "r"(b0), "r"(b1));
}

__device__ __forceinline__ float fuse1(float a, float b, float c,
                                       float ia, float ib, float ic,
                                       bool unitw, float w0, float w1, float w2, float fb)
{
    float ps = fminf(fmaxf(a*ia, EPSV), 1.f-EPSV);
    float pc = fminf(fmaxf(b*ib, EPSV), 1.f-EPSV);
    float pp = fminf(fmaxf(c*ic, EPSV), 1.f-EPSV);
    if (unitw) {
        float num = ps*pc*pp;
        float den = (1.f-ps+EPSV)*(1.f-pc+EPSV)*(1.f-pp+EPSV);
        return __fdividef(num, num + den);
    }
    float L0 = __logf(__fdividef(ps, 1.f-ps+EPSV));
    float L1 = __logf(__fdividef(pc, 1.f-pc+EPSV));
    float L2 = __logf(__fdividef(pp, 1.f-pp+EPSV));
    float logit = fb + w0*L0 + w1*L1 + w2*L2;
    return __fdividef(1.f, 1.f+__expf(-logit));
}

#define HKS 4                     // split-K factor
#define HKC (SS/HKS)              // 256 k per block

__global__ __launch_bounds__(256) void fused_hop_gemm_kernel(
    const float* __restrict__ fusion_w, const float* __restrict__ fusion_b)
{
    __shared__ float As[16][132];   // [k][m] fused values (tf32)
    __shared__ float Bs[16][68];    // [k][n]
    __shared__ float irs_a[128], irs_c[128], irs_p[128], frs_s[128];
    int tid = threadIdx.x;
    int warp = tid >> 5, lane = tid & 31;
    int hop = blockIdx.z >> 2, kc = blockIdx.z & 3;
    int b = blockIdx.y, m0 = blockIdx.x*128;

    const float *Ms, *Mc, *Mp;
    if (hop == 0) { Ms = g_A;  Mc = g_P;  Mp = g_Qm; }
    else          { Ms = g_A2; Mc = g_P2; Mp = g_Q2; }
    float w0 = fusion_w[hop*3+0], w1 = fusion_w[hop*3+1], w2 = fusion_w[hop*3+2];
    float fb = fusion_b[hop];
    bool unitw = (w0 == 1.f) && (w1 == 1.f) && (w2 == 1.f) && (fb == 0.f);

    size_t rowbase = (size_t)b*SS + m0;
    if (tid < 128) {
        if (hop == 0) irs_a[tid] = 1.f/(1.f + EPSV);
        else          irs_a[tid] = 1.f/(g_rs[(size_t)3*NTOK + rowbase + tid] + EPSV);
        irs_c[tid] = 1.f/(g_rs[(size_t)(hop ? 4 : 1)*NTOK + rowbase + tid] + EPSV);
        irs_p[tid] = 1.f/(g_rs[(size_t)(hop ? 5 : 2)*NTOK + rowbase + tid] + EPSV);
        frs_s[tid] = 0.f;
    }
    __syncthreads();

    const float* Bg = g_hopvT + (size_t)(hop*NB + b)*DD*SS;
    float* Hg = g_H + (size_t)hop*NTOK*DD + (size_t)b*SS*DD;

    int wr = warp >> 1, wc = warp & 1;     // 4 x 2 warps, tile 32(m) x 32(n)
    int group = lane >> 2, tig = lane & 3;

    float acc[2][4][4];
    #pragma unroll
    for (int i = 0; i < 2; i++)
        #pragma unroll
        for (int j = 0; j < 4; j++) {
            acc[i][j][0]=0; acc[i][j][1]=0; acc[i][j][2]=0; acc[i][j][3]=0;
        }

    int kk = tid & 15, msi = tid >> 4;     // staging indices
    for (int k0 = kc*HKC; k0 < kc*HKC + HKC; k0 += 16) {
        #pragma unroll
        for (int p = 0; p < 8; p++) {
            int m = msi + p*16;
            size_t off = (rowbase + m)*SS + k0 + kk;
            float f = fuse1(Ms[off], Mc[off], Mp[off],
                            irs_a[m], irs_c[m], irs_p[m],
                            unitw, w0, w1, w2, fb);
            As[kk][m] = to_tf32(f);
            atomicAdd(&frs_s[m], f);
        }
        #pragma unroll
        for (int p = 0; p < 4; p++)
            Bs[kk][msi + p*16] = to_tf32(Bg[(size_t)(msi + p*16)*SS + k0 + kk]);
        __syncthreads();
        #pragma unroll
        for (int ks = 0; ks < 2; ks++) {
            int kb = ks * 8;
            uint32_t af[2][4], bf[4][2];
            #pragma unroll
            for (int mi = 0; mi < 2; mi++) {
                int mb = wr*32 + mi*16 + group;
                af[mi][0] = __float_as_uint(As[kb+tig  ][mb]);
                af[mi][1] = __float_as_uint(As[kb+tig  ][mb+8]);
                af[mi][2] = __float_as_uint(As[kb+tig+4][mb]);
                af[mi][3] = __float_as_uint(As[kb+tig+4][mb+8]);
            }
            #pragma unroll
            for (int nj = 0; nj < 4; nj++) {
                int nb = wc*32 + nj*8 + group;
                bf[nj][0] = __float_as_uint(Bs[kb+tig  ][nb]);
                bf[nj][1] = __float_as_uint(Bs[kb+tig+4][nb]);
            }
            #pragma unroll
            for (int mi = 0; mi < 2; mi++)
                #pragma unroll
                for (int nj = 0; nj < 4; nj++)
                    mma_tf32(acc[mi][nj], af[mi][0], af[mi][1], af[mi][2], af[mi][3],
                             bf[nj][0], bf[nj][1]);
        }
        __syncthreads();
    }

    #pragma unroll
    for (int mi = 0; mi < 2; mi++)
        #pragma unroll
        for (int nj = 0; nj < 4; nj++) {
            int row = m0 + wr*32 + mi*16 + group;
            int col = wc*32 + nj*8 + 2*tig;
            atomicAdd(&Hg[(size_t)row*DD + col],     acc[mi][nj][0]);
            atomicAdd(&Hg[(size_t)row*DD + col + 1], acc[mi][nj][1]);
            atomicAdd(&Hg[(size_t)(row+8)*DD + col],     acc[mi][nj][2]);
            atomicAdd(&Hg[(size_t)(row+8)*DD + col + 1], acc[mi][nj][3]);
        }

    if (tid < 128)
        atomicAdd(&g_frs[(size_t)hop*NTOK + rowbase + tid], frs_s[tid]);
}

// ---------------- 9) out = (gate-combined H) @ out_W^T ----------------
__global__ __launch_bounds__(256) void outproj_kernel(
    const float* __restrict__ outW, float* __restrict__ out)
{
    __shared__ float cs[16][65];
    __shared__ float ws[128][65];
    int tb = blockIdx.x * 16;
    int tid = threadIdx.x;
    #pragma unroll
    for (int e = tid; e < 16*64; e += 256) {
        int tl = e >> 6, ee = e & 63;
        int tok = tb + tl;
        float s0 = __fdividef(g_gate[tok*2+0], g_frs[tok] + EPSV);
        float s1 = __fdividef(g_gate[tok*2+1], g_frs[NTOK + tok] + EPSV);
        cs[tl][ee] = s0*g_H[(size_t)tok*DD + ee]
                   + s1*g_H[(size_t)NTOK*DD + (size_t)tok*DD + ee];
    }
    int tk2 = tid >> 5;
    int h4  = tid & 31;
    for (int hc = 0; hc < 4; hc++) {
        __syncthreads();
        #pragma unroll
        for (int e = tid; e < 128*64; e += 256)
            ws[e>>6][e&63] = outW[(size_t)hc*128*DD + e];
        __syncthreads();
        float a0[4] = {0,0,0,0}, a1[4] = {0,0,0,0};
        #pragma unroll 4
        for (int d = 0; d < 64; d++) {
            float c0 = cs[2*tk2][d], c1 = cs[2*tk2+1][d];
            #pragma unroll
            for (int j = 0; j < 4; j++) {
                float w = ws[h4*4 + j][d];
                a0[j] += c0*w; a1[j] += c1*w;
            }
        }
        *(float4*)&out[(size_t)(tb + 2*tk2)*HID + hc*128 + h4*4] =
            make_float4(a0[0], a0[1], a0[2], a0[3]);
        *(float4*)&out[(size_t)(tb + 2*tk2 + 1)*HID + hc*128 + h4*4] =
            make_float4(a1[0], a1[1], a1[2], a1[3]);
    }
}

// ---------------- launch ----------------
extern "C" void kernel_launch(void* const* d_in, const int* in_sizes, int n_in,
                              void* d_out, int out_size)
{
    const float* x      = (const float*)d_in[0];
    const float* Wq     = (const float*)d_in[1];
    const float* Wk     = (const float*)d_in[2];
    const float* Wv     = (const float*)d_in[3];
    const float* btab   = (const float*)d_in[4];
    const float* fw     = (const float*)d_in[5];
    const float* fbias  = (const float*)d_in[6];
    const float* hopW   = (const float*)d_in[7];
    const float* gateW  = (const float*)d_in[8];
    const float* gateb  = (const float*)d_in[9];
    const float* outW   = (const float*)d_in[10];
    const float* temp   = (const float*)d_in[11];
    const int*   relidx = (const int*)d_in[12];
    float* out = (float*)d_out;

    cudaFuncSetAttribute(gemm_bf16_kernel,
                         cudaFuncAttributeMaxDynamicSharedMemorySize, GEMM_DSMEM);

    zero_kernel<<<ZERO_BLOCKS, 256>>>();
    proj_kernel<<<NTOK/TOK_PB, 256>>>(x, Wq, Wk, Wv, gateW);
    rope_kernel<<<(NTOK*32)/256, 256>>>();
    hopv_gate_kernel<<<dim3(NTOK/64, 4), 256>>>(hopW, gateb);
    scores_kernel<<<dim3(16,16,NB), 256>>>(btab, relidx, temp);
    softmax_kernel<<<NTOK, 256>>>();
    transpose_kernel<<<dim3(32,32,NB), 256>>>();

    // hmat: 0=Ah 1=Th 2=Ph 3=Qmh ; mat: 1=P 2=Qm 3=A2 4=P2 5=Q2
    gemm_bf16_kernel<<<dim3(36,1,NB), 256, GEMM_DSMEM>>>(0,0,1, 2, 1); // P  = Ah Ah^T (tri)
    gemm_bf16_kernel<<<dim3(36,1,NB), 256, GEMM_DSMEM>>>(1,1,2, 3, 1); // Qm = Th Th^T (tri)
    gemm_bf16_kernel<<<dim3(64,1,NB), 256, GEMM_DSMEM>>>(0,1,3,-1, 0); // A2 = Ah Th^T (full)
    mirror2_kernel<<<dim3(28,32,NB), 256>>>(1, 2, 2, 3);               // P(+Ph), Qm(+Qmh)
    gemm_bf16_kernel<<<dim3(36,1,NB), 256, GEMM_DSMEM>>>(2,2,4,-1, 1); // P2 = Ph Ph^T (tri)
    gemm_bf16_kernel<<<dim3(36,1,NB), 256, GEMM_DSMEM>>>(3,3,5,-1, 1); // Q2 = Qmh Qmh^T (tri)
    mirror2_kernel<<<dim3(28,32,NB), 256>>>(4, -1, 5, -1);             // P2, Q2

    fused_hop_gemm_kernel<<<dim3(8, NB, HKS*2), 256>>>(fw, fbias);
    outproj_kernel<<<NTOK/16, 256>>>(outW, out);
}

// round 15
// speedup vs baseline: 1.1338x; 1.1338x over previous
#include <cuda_runtime.h>
#include <cuda_bf16.h>
#include <cstdint>

#define NB 8
#define SS 1024
#define DD 64
#define HID 512
#define NTOK (NB*SS)          // 8192
#define EPSV 1e-6f

// ---------------- device scratch (no allocation allowed) ----------------
__device__ float g_Q[NTOK*DD];
__device__ float g_K[NTOK*DD];
__device__ float g_V[NTOK*DD];
__device__ float g_gate[NTOK*2];
__device__ float g_rs[6*NTOK];           // rowsums: slots 1..5 = P,Qm,A2,P2,Q2
__device__ float g_frs[2*NTOK];          // rowsums of fused matrices (atomic)
__device__ float g_H[2*NTOK*DD];         // hop outputs (pre-norm, atomic)
__device__ float g_A [(size_t)NB*SS*SS]; // softmax attention
__device__ float g_P [(size_t)NB*SS*SS]; // A A^T
__device__ float g_Qm[(size_t)NB*SS*SS]; // A^T A
__device__ float g_A2[(size_t)NB*SS*SS]; // A A
__device__ float g_P2[(size_t)NB*SS*SS]; // P P
__device__ float g_Q2[(size_t)NB*SS*SS]; // Qm Qm
__device__ float g_hopvT[2*(size_t)NB*DD*SS]; // hopv transposed, k-major, fp32
// bf16 GEMM operands
__device__ __nv_bfloat16 g_Ah [(size_t)NB*SS*SS];
__device__ __nv_bfloat16 g_Th [(size_t)NB*SS*SS];
__device__ __nv_bfloat16 g_Ph [(size_t)NB*SS*SS];
__device__ __nv_bfloat16 g_Qmh[(size_t)NB*SS*SS];

__device__ __forceinline__ float* matsel(int s) {
    switch (s) {
        case 0: return g_A;
        case 1: return g_P;
        case 2: return g_Qm;
        case 3: return g_A2;
        case 4: return g_P2;
        default: return g_Q2;
    }
}
__device__ __forceinline__ __nv_bfloat16* hmatsel(int s) {
    switch (s) {
        case 0: return g_Ah;
        case 1: return g_Th;
        case 2: return g_Ph;
        default: return g_Qmh;
    }
}

__device__ __forceinline__ float warp_max(float v) {
    #pragma unroll
    for (int o = 16; o > 0; o >>= 1) v = fmaxf(v, __shfl_xor_sync(0xffffffffu, v, o));
    return v;
}
__device__ __forceinline__ float warp_sum(float v) {
    #pragma unroll
    for (int o = 16; o > 0; o >>= 1) v += __shfl_xor_sync(0xffffffffu, v, o);
    return v;
}

// ---------------- 0) zero g_rs + g_frs + g_H ----------------
#define ZTOT ((6*NTOK + 2*NTOK + 2*NTOK*DD)/4)
__global__ void zero_kernel()
{
    int gid = blockIdx.x*256 + threadIdx.x;   // float4 index
    if (gid >= ZTOT) return;
    if (gid < 6*NTOK/4)
        ((float4*)g_rs)[gid] = make_float4(0.f,0.f,0.f,0.f);
    else if (gid < (6*NTOK + 2*NTOK)/4)
        ((float4*)g_frs)[gid - 6*NTOK/4] = make_float4(0.f,0.f,0.f,0.f);
    else
        ((float4*)g_H)[gid - (6*NTOK + 2*NTOK)/4] = make_float4(0.f,0.f,0.f,0.f);
}
#define ZERO_BLOCKS ((ZTOT + 255)/256)

// ---------------- 1) QKV + gate-logit projection ----------------
#define TOK_PB 16
__global__ __launch_bounds__(256) void proj_kernel(
    const float* __restrict__ x, const float* __restrict__ Wq,
    const float* __restrict__ Wk, const float* __restrict__ Wv,
    const float* __restrict__ gW)
{
    __shared__ float xs[TOK_PB*HID];
    int tb = blockIdx.x * TOK_PB;
    int tid = threadIdx.x;
    const float4* xg = (const float4*)(x + (size_t)tb*HID);
    float4* xs4 = (float4*)xs;
    #pragma unroll
    for (int i = tid; i < TOK_PB*HID/4; i += 256) xs4[i] = xg[i];
    __syncthreads();

    for (int o = tid; o < TOK_PB*194; o += 256) {
        int tok = o / 194, ch = o % 194;
        const float* w;
        if (ch < 64)       w = Wq + ch*HID;
        else if (ch < 128) w = Wk + (ch-64)*HID;
        else if (ch < 192) w = Wv + (ch-128)*HID;
        else               w = gW + (ch-192)*HID;
        const float4* w4  = (const float4*)w;
        const float4* xv4 = (const float4*)(xs + tok*HID);
        float acc = 0.f;
        #pragma unroll 8
        for (int k = 0; k < HID/4; k++) {
            float4 a = xv4[k];
            float4 b = __ldg(&w4[k]);
            acc += a.x*b.x + a.y*b.y + a.z*b.z + a.w*b.w;
        }
        size_t gt = tb + tok;
        if (ch < 64)       g_Q[gt*DD + ch]        = acc;
        else if (ch < 128) g_K[gt*DD + (ch-64)]   = acc;
        else if (ch < 192) g_V[gt*DD + (ch-128)]  = acc;
        else               g_gate[gt*2 + (ch-192)] = acc;
    }
}

// ---------------- 2) RoPE in place on Q,K ----------------
__global__ void rope_kernel()
{
    int gid = blockIdx.x*256 + threadIdx.x;
    if (gid >= NTOK*32) return;
    int tok = gid >> 5, j = gid & 31;
    int s = tok & (SS-1);
    float invf = (float)exp(-log(10000.0) * (double)j / 32.0);
    float ang = (float)s * invf;
    float sn, cs;
    sincosf(ang, &sn, &cs);
    size_t base = (size_t)tok * DD;
    float q0 = g_Q[base+j], q1 = g_Q[base+j+32];
    g_Q[base+j]    = q0*cs - q1*sn;
    g_Q[base+j+32] = q1*cs + q0*sn;
    float k0 = g_K[base+j], k1 = g_K[base+j+32];
    g_K[base+j]    = k0*cs - k1*sn;
    g_K[base+j+32] = k1*cs + k0*sn;
}

// ---------------- 3) hopvT (coalesced, e-split) ; gate softmax ----------------
__global__ __launch_bounds__(256) void hopv_gate_kernel(
    const float* __restrict__ hopW, const float* __restrict__ gateb)
{
    __shared__ float vs[64][65];
    int t0tok = blockIdx.x * 64;
    int eq = blockIdx.y;                       // e quarter 0..3
    int b = t0tok >> 10, s0 = t0tok & (SS-1);
    int tid = threadIdx.x;

    #pragma unroll
    for (int i = tid; i < 64*16; i += 256) {   // float4 granules
        int tokL = i >> 4;
        int d4 = (i & 15) * 4;
        float4 v = *(const float4*)(g_V + (size_t)(t0tok + tokL)*DD + d4);
        vs[tokL][d4] = v.x; vs[tokL][d4+1] = v.y;
        vs[tokL][d4+2] = v.z; vs[tokL][d4+3] = v.w;
    }
    __syncthreads();

    int tokL = tid & 63;
    int e0 = eq*16 + (tid >> 6);               // 4 e per block-thread-group
    int s = s0 + tokL;
    #pragma unroll 4
    for (int e = e0; e < eq*16 + 16; e += 4) {
        const float* w0 = hopW + e*DD;
        const float* w1 = hopW + DD*DD + e*DD;
        float a0 = 0.f, a1 = 0.f;
        #pragma unroll
        for (int d = 0; d < DD; d++) {
            float v = vs[tokL][d];
            a0 += v * __ldg(&w0[d]);
            a1 += v * __ldg(&w1[d]);
        }
        g_hopvT[((size_t)b*DD + e)*SS + s] = a0;
        g_hopvT[((size_t)(NB + b)*DD + e)*SS + s] = a1;
    }

    if (eq == 0 && tid < 64) {
        int tok = t0tok + tid;
        float l0 = g_gate[tok*2]   + __ldg(&gateb[0]);
        float l1 = g_gate[tok*2+1] + __ldg(&gateb[1]);
        float m = fmaxf(l0, l1);
        float e0v = __expf(l0-m), e1v = __expf(l1-m);
        float inv = 1.f/(e0v+e1v);
        g_gate[tok*2]   = e0v*inv;
        g_gate[tok*2+1] = e1v*inv;
    }
}

// ---------------- 4) scores ----------------
__global__ __launch_bounds__(256) void scores_kernel(
    const float* __restrict__ bias_table, const int* __restrict__ rel_idx,
    const float* __restrict__ temperature)
{
    __shared__ float qs[64][65];
    __shared__ float ks[64][65];
    int b = blockIdx.z;
    int s0 = blockIdx.y * 64, t0 = blockIdx.x * 64;
    int tid = threadIdx.x;
    const float* Qb = g_Q + ((size_t)b*SS + s0)*DD;
    const float* Kb = g_K + ((size_t)b*SS + t0)*DD;
    #pragma unroll
    for (int e = tid; e < 64*64; e += 256) {
        qs[e>>6][e&63] = Qb[e];
        ks[e>>6][e&63] = Kb[e];
    }
    __syncthreads();
    int ty = tid >> 4, tx = tid & 15;
    float c[4][4];
    #pragma unroll
    for (int i=0;i<4;i++) { c[i][0]=0;c[i][1]=0;c[i][2]=0;c[i][3]=0; }
    #pragma unroll 4
    for (int d = 0; d < 64; d++) {
        float rq[4], rk[4];
        #pragma unroll
        for (int i=0;i<4;i++) { rq[i] = qs[ty*4+i][d]; rk[i] = ks[tx*4+i][d]; }
        #pragma unroll
        for (int i=0;i<4;i++)
            #pragma unroll
            for (int j=0;j<4;j++) c[i][j] += rq[i]*rk[j];
    }
    float inv_t = 1.f / fmaxf(temperature[0], 0.1f);
    const float scale = 0.125f;
    float* Ab = g_A + (size_t)b*SS*SS;
    #pragma unroll
    for (int i = 0; i < 4; i++) {
        int s = s0 + ty*4 + i;
        int4 idx = *(const int4*)(rel_idx + (size_t)s*SS + t0 + tx*4);
        float4 out;
        out.x = (c[i][0]*scale + __ldg(&bias_table[idx.x])) * inv_t;
        out.y = (c[i][1]*scale + __ldg(&bias_table[idx.y])) * inv_t;
        out.z = (c[i][2]*scale + __ldg(&bias_table[idx.z])) * inv_t;
        out.w = (c[i][3]*scale + __ldg(&bias_table[idx.w])) * inv_t;
        *(float4*)(Ab + (size_t)s*SS + t0 + tx*4) = out;
    }
}

// ---------------- 5) row softmax in place on g_A (+ bf16 copy) ----------------
__global__ __launch_bounds__(256) void softmax_kernel()
{
    size_t row = blockIdx.x;
    float* Ar = g_A + row*SS;
    __nv_bfloat16* Ah = g_Ah + row*SS;
    int tid = threadIdx.x;
    int wid = tid >> 5, lane = tid & 31;
    __shared__ float sm[8];
    float4 v = ((float4*)Ar)[tid];
    float m = fmaxf(fmaxf(v.x, v.y), fmaxf(v.z, v.w));
    m = warp_max(m);
    if (lane == 0) sm[wid] = m;
    __syncthreads();
    if (wid == 0) {
        float t = (lane < 8) ? sm[lane] : -3.4e38f;
        t = warp_max(t);
        if (lane == 0) sm[0] = t;
    }
    __syncthreads();
    m = sm[0];
    __syncthreads();
    float e0 = __expf(v.x-m), e1 = __expf(v.y-m), e2 = __expf(v.z-m), e3 = __expf(v.w-m);
    float s = e0+e1+e2+e3;
    s = warp_sum(s);
    if (lane == 0) sm[wid] = s;
    __syncthreads();
    if (wid == 0) {
        float t = (lane < 8) ? sm[lane] : 0.f;
        t = warp_sum(t);
        if (lane == 0) sm[0] = t;
    }
    __syncthreads();
    float inv = 1.f / sm[0];
    float4 o = make_float4(e0*inv, e1*inv, e2*inv, e3*inv);
    ((float4*)Ar)[tid] = o;
    __nv_bfloat162 h0 = __floats2bfloat162_rn(o.x, o.y);
    __nv_bfloat162 h1 = __floats2bfloat162_rn(o.z, o.w);
    ((__nv_bfloat162*)Ah)[tid*2]   = h0;
    ((__nv_bfloat162*)Ah)[tid*2+1] = h1;
}

// ---------------- 5b) transpose: g_Th = (g_Ah)^T per batch (bf16 in/out) ----------------
__global__ __launch_bounds__(256) void transpose_kernel()
{
    __shared__ __nv_bfloat16 t[32][34];
    int b = blockIdx.z;
    int x0 = blockIdx.x*32, y0 = blockIdx.y*32;
    const __nv_bfloat16* Ab = g_Ah + (size_t)b*SS*SS;
    __nv_bfloat16* Tb = g_Th + (size_t)b*SS*SS;
    int tx = threadIdx.x & 31, ty = threadIdx.x >> 5;   // 32 x 8
    #pragma unroll
    for (int i = 0; i < 32; i += 8)
        t[ty+i][tx] = Ab[(size_t)(y0+ty+i)*SS + x0+tx];
    __syncthreads();
    #pragma unroll
    for (int i = 0; i < 32; i += 8)
        Tb[(size_t)(x0+ty+i)*SS + y0+tx] = t[tx][ty+i];
}

// ================= bf16 mma.sync batched NT GEMM (+rowsum epilogue) =================
__device__ __forceinline__ uint32_t s2u(const void* p) {
    uint32_t a;
    asm("{ .reg .u64 t; cvta.to.shared.u64 t, %1; cvt.u32.u64 %0, t; }" : "=r"(a) : "l"(p));
    return a;
}
#define SWZ(o) ((o) ^ (((o)>>3)&0x70))

__device__ __forceinline__ void cp16(uint32_t dst, const void* src) {
    asm volatile("cp.async.cg.shared.global [%0], [%1], 16;" :: "r"(dst), "l"(src));
}
__device__ __forceinline__ void cp_commit() { asm volatile("cp.async.commit_group;" ::: "memory"); }
#define CP_WAIT(n) asm volatile("cp.async.wait_group %0;" :: "n"(n) : "memory")

__device__ __forceinline__ void ldsm4(uint32_t* r, uint32_t addr) {
    asm volatile("ldmatrix.sync.aligned.m8n8.x4.shared.b16 {%0,%1,%2,%3}, [%4];"
        : "=r"(r[0]), "=r"(r[1]), "=r"(r[2]), "=r"(r[3]) : "r"(addr));
}
__device__ __forceinline__ void mma_bf16(float* c, const uint32_t* a,
                                         uint32_t b0, uint32_t b1) {
    asm volatile(
        "mma.sync.aligned.m16n8k16.row.col.f32.bf16.bf16.f32 "
        "{%0,%1,%2,%3},{%4,%5,%6,%7},{%8,%9},{%0,%1,%2,%3};"
        : "+f"(c[0]), "+f"(c[1]), "+f"(c[2]), "+f"(c[3])
        : "r"(a[0]), "r"(a[1]), "r"(a[2]), "r"(a[3]), "r"(b0), "r"(b1));
}

#define STG 3
#define CK 64                        // k per chunk (bf16): 128B per row
#define NCH (SS/CK)                  // 16
#define STAGE_BYTES 32768
#define GEMM_DSMEM (STG*STAGE_BYTES) // 98304

__global__ __launch_bounds__(256, 2)
void gemm_bf16_kernel(int asel, int bsel, int cfsel, int chsel, int tri)
{
    extern __shared__ __align__(16) char dsmem[];
    uint32_t sb = s2u(dsmem);
    int tid = threadIdx.x;
    int warp = tid >> 5, lane = tid & 31;

    size_t off = (size_t)blockIdx.z*SS*SS;
    const __nv_bfloat16* Ag = hmatsel(asel) + off;
    const __nv_bfloat16* Bg = hmatsel(bsel) + off;
    float* Cg = matsel(cfsel) + off;
    __nv_bfloat16* Chg = (chsel >= 0) ? hmatsel(chsel) + off : nullptr;

    int bi, bj;
    if (tri) {
        int t = blockIdx.x, i = 0;
        while (t >= 8 - i) { t -= 8 - i; i++; }
        bi = i; bj = i + t;
    } else {
        bi = blockIdx.x >> 3; bj = blockIdx.x & 7;
    }
    int m0 = bi*128, n0 = bj*128;
    bool same = (tri != 0) && (bi == bj) && (asel == bsel);
    uint32_t bBase = same ? 0u : 16384u;

    int wm = (warp >> 2)*64, wn = (warp & 3)*32;
    int rlane = (lane & 7) + ((lane >> 3) & 1)*8;
    int clane = (lane >> 4) & 1;

    float acc[4][4][4];
    #pragma unroll
    for (int i = 0; i < 4; i++)
        #pragma unroll
        for (int j = 0; j < 4; j++) {
            acc[i][j][0]=0; acc[i][j][1]=0; acc[i][j][2]=0; acc[i][j][3]=0;
        }

    auto load_chunk = [&](int c) {
        uint32_t stg = sb + (uint32_t)(c % STG) * STAGE_BYTES;
        int k0 = c * CK;
        #pragma unroll
        for (int it = 0; it < 8; it++) {
            int u = tid + it*256;
            int r = u >> 3;
            int ch = u & 7;
            if (r < 128) {
                const __nv_bfloat16* gsrc = Ag + (size_t)(m0 + r)*SS + k0 + ch*8;
                cp16(stg + SWZ((uint32_t)(r*128 + ch*16)), gsrc);
            } else if (!same) {
                const __nv_bfloat16* gsrc = Bg + (size_t)(n0 + (r-128))*SS + k0 + ch*8;
                cp16(stg + 16384u + SWZ((uint32_t)((r-128)*128 + ch*16)), gsrc);
            }
        }
    };

    for (int c = 0; c < STG-1; c++) { load_chunk(c); cp_commit(); }

    for (int c = 0; c < NCH; c++) {
        int lc = c + STG - 1;
        if (lc < NCH) load_chunk(lc);
        cp_commit();
        CP_WAIT(STG-1);
        __syncthreads();
        uint32_t stg = sb + (uint32_t)(c % STG) * STAGE_BYTES;
        #pragma unroll
        for (int ks = 0; ks < CK/16; ks++) {
            uint32_t af[4][4], bfr[2][4];
            int kch = ks*2 + clane;
            #pragma unroll
            for (int mi = 0; mi < 4; mi++) {
                int r = wm + mi*16 + rlane;
                ldsm4(af[mi], stg + SWZ((uint32_t)(r*128 + kch*16)));
            }
            #pragma unroll
            for (int nt = 0; nt < 2; nt++) {
                int r = wn + nt*16 + rlane;
                ldsm4(bfr[nt], stg + bBase + SWZ((uint32_t)(r*128 + kch*16)));
            }
            #pragma unroll
            for (int mi = 0; mi < 4; mi++)
                #pragma unroll
                for (int nj = 0; nj < 4; nj++) {
                    int nt = nj >> 1, sel = nj & 1;
                    mma_bf16(acc[mi][nj], af[mi], bfr[nt][sel], bfr[nt][sel+2]);
                }
        }
        __syncthreads();
    }

    int rr = lane >> 2, cc2 = (lane & 3)*2;
    #pragma unroll
    for (int mi = 0; mi < 4; mi++) {
        #pragma unroll
        for (int nj = 0; nj < 4; nj++) {
            int row = m0 + wm + mi*16 + rr;
            int col = n0 + wn + nj*8 + cc2;
            float2 v01 = make_float2(acc[mi][nj][0], acc[mi][nj][1]);
            float2 v23 = make_float2(acc[mi][nj][2], acc[mi][nj][3]);
            *(float2*)&Cg[(size_t)row*SS + col]     = v01;
            *(float2*)&Cg[(size_t)(row+8)*SS + col] = v23;
            if (Chg) {
                *(__nv_bfloat162*)&Chg[(size_t)row*SS + col] =
                    __floats2bfloat162_rn(v01.x, v01.y);
                *(__nv_bfloat162*)&Chg[(size_t)(row+8)*SS + col] =
                    __floats2bfloat162_rn(v23.x, v23.y);
            }
        }
    }

    // ---- rowsum epilogue: slot index == cfsel ----
    float* rs = g_rs + (size_t)cfsel*NTOK + (size_t)blockIdx.z*SS;
    #pragma unroll
    for (int mi = 0; mi < 4; mi++) {
        float r0 = 0.f, r1 = 0.f;
        #pragma unroll
        for (int nj = 0; nj < 4; nj++) {
            r0 += acc[mi][nj][0] + acc[mi][nj][1];
            r1 += acc[mi][nj][2] + acc[mi][nj][3];
        }
        r0 += __shfl_xor_sync(0xffffffffu, r0, 1);
        r0 += __shfl_xor_sync(0xffffffffu, r0, 2);
        r1 += __shfl_xor_sync(0xffffffffu, r1, 1);
        r1 += __shfl_xor_sync(0xffffffffu, r1, 2);
        if ((lane & 3) == 0) {
            int row = m0 + wm + mi*16 + rr;
            atomicAdd(&rs[row], r0);
            atomicAdd(&rs[row+8], r1);
        }
    }
    if (tri && bi != bj) {
        #pragma unroll
        for (int nj = 0; nj < 4; nj++) {
            float c0 = 0.f, c1 = 0.f;
            #pragma unroll
            for (int mi = 0; mi < 4; mi++) {
                c0 += acc[mi][nj][0] + acc[mi][nj][2];
                c1 += acc[mi][nj][1] + acc[mi][nj][3];
            }
            c0 += __shfl_xor_sync(0xffffffffu, c0, 4);
            c0 += __shfl_xor_sync(0xffffffffu, c0, 8);
            c0 += __shfl_xor_sync(0xffffffffu, c0, 16);
            c1 += __shfl_xor_sync(0xffffffffu, c1, 4);
            c1 += __shfl_xor_sync(0xffffffffu, c1, 8);
            c1 += __shfl_xor_sync(0xffffffffu, c1, 16);
            if (lane < 4) {
                int col = n0 + wn + nj*8 + cc2;
                atomicAdd(&rs[col], c0);
                atomicAdd(&rs[col+1], c1);
            }
        }
    }
}

// ---------------- 6b) mirror lower triangle of two symmetric matrices ----------------
__global__ __launch_bounds__(256) void mirror2_kernel(
    int m0sel, int h0sel, int m1sel, int h1sel)
{
    __shared__ float t[32][33];
    size_t off = (size_t)blockIdx.z*SS*SS;
    int which = blockIdx.y >> 4;
    int msel = which ? m1sel : m0sel;
    int hsel = which ? h1sel : h0sel;
    float* M = matsel(msel) + off;
    __nv_bfloat16* Mh = (hsel >= 0) ? hmatsel(hsel) + off : nullptr;

    int p = blockIdx.x, i = 0;
    while (p >= 7 - i) { p -= 7 - i; i++; }
    int j = i + 1 + p;
    int sub = blockIdx.y & 15;
    int y0 = i*128 + (sub >> 2)*32;
    int x0 = j*128 + (sub & 3)*32;
    int tx = threadIdx.x & 31, ty = threadIdx.x >> 5;
    #pragma unroll
    for (int k = 0; k < 32; k += 8)
        t[ty+k][tx] = M[(size_t)(y0+ty+k)*SS + x0+tx];
    __syncthreads();
    #pragma unroll
    for (int k = 0; k < 32; k += 8) {
        float v = t[tx][ty+k];
        size_t dst = (size_t)(x0+ty+k)*SS + y0+tx;
        M[dst] = v;
        if (Mh) Mh[dst] = __float2bfloat16(v);
    }
}

// ---------------- 8) fused F-compute + hop GEMM (TF32, split-K x4) ----------------
__device__ __forceinline__ float to_tf32(float x) {
    uint32_t u;
    asm("cvt.rna.tf32.f32 %0, %1;" : "=r"(u) : "f"(x));
    return __uint_as_float(u);
}
__device__ __forceinline__ void mma_tf32(float* c,
    uint32_t a0, uint32_t a1, uint32_t a2, uint32_t a3, uint32_t b0, uint32_t b1)
{
    asm volatile(
        "mma.sync.aligned.m16n8k8.row.col.f32.tf32.tf32.f32 "
        "{%0,%1,%2,%3},{%4,%5,%6,%7},{%8,%9},{%0,%1,%2,%3};"
        : "+f"(c[0]), "+f"(c[1]), "+f"(c[2]), "+f"(c[3])
        : "r"(a0), "r"(a1), "r"(a2), "r"(a3), "r"(b0), "r"(b1));
}

__device__ __forceinline__ float fuse1(float a, float b, float c,
                                       float ia, float ib, float ic,
                                       bool unitw, float w0, float w1, float w2, float fb)
{
    float ps = fminf(fmaxf(a*ia, EPSV), 1.f-EPSV);
    float pc = fminf(fmaxf(b*ib, EPSV), 1.f-EPSV);
    float pp = fminf(fmaxf(c*ic, EPSV), 1.f-EPSV);
    if (unitw) {
        float num = ps*pc*pp;
        float den = (1.f-ps+EPSV)*(1.f-pc+EPSV)*(1.f-pp+EPSV);
        return __fdividef(num, num + den);
    }
    float L0 = __logf(__fdividef(ps, 1.f-ps+EPSV));
    float L1 = __logf(__fdividef(pc, 1.f-pc+EPSV));
    float L2 = __logf(__fdividef(pp, 1.f-pp+EPSV));
    float logit = fb + w0*L0 + w1*L1 + w2*L2;
    return __fdividef(1.f, 1.f+__expf(-logit));
}

#define HKS 4                     // split-K factor
#define HKC (SS/HKS)              // 256 k per block

__global__ __launch_bounds__(256) void fused_hop_gemm_kernel(
    const float* __restrict__ fusion_w, const float* __restrict__ fusion_b)
{
    __shared__ float As[16][132];   // [k][m] fused values (tf32)
    __shared__ float Bs[16][68];    // [k][n]
    __shared__ float irs_a[128], irs_c[128], irs_p[128];
    int tid = threadIdx.x;
    int warp = tid >> 5, lane = tid & 31;
    int hop = blockIdx.z >> 2, kc = blockIdx.z & 3;
    int b = blockIdx.y, m0 = blockIdx.x*128;

    const float *Ms, *Mc, *Mp;
    if (hop == 0) { Ms = g_A;  Mc = g_P;  Mp = g_Qm; }
    else          { Ms = g_A2; Mc = g_P2; Mp = g_Q2; }
    float w0 = fusion_w[hop*3+0], w1 = fusion_w[hop*3+1], w2 = fusion_w[hop*3+2];
    float fb = fusion_b[hop];
    bool unitw = (w0 == 1.f) && (w1 == 1.f) && (w2 == 1.f) && (fb == 0.f);

    size_t rowbase = (size_t)b*SS + m0;
    if (tid < 128) {
        if (hop == 0) irs_a[tid] = 1.f/(1.f + EPSV);
        else          irs_a[tid] = 1.f/(g_rs[(size_t)3*NTOK + rowbase + tid] + EPSV);
        irs_c[tid] = 1.f/(g_rs[(size_t)(hop ? 4 : 1)*NTOK + rowbase + tid] + EPSV);
        irs_p[tid] = 1.f/(g_rs[(size_t)(hop ? 5 : 2)*NTOK + rowbase + tid] + EPSV);
    }
    __syncthreads();

    const float* Bg = g_hopvT + (size_t)(hop*NB + b)*DD*SS;
    float* Hg = g_H + (size_t)hop*NTOK*DD + (size_t)b*SS*DD;

    int wr = warp >> 1, wc = warp & 1;     // 4 x 2 warps, tile 32(m) x 32(n)
    int group = lane >> 2, tig = lane & 3;

    float acc[2][4][4];
    #pragma unroll
    for (int i = 0; i < 2; i++)
        #pragma unroll
        for (int j = 0; j < 4; j++) {
            acc[i][j][0]=0; acc[i][j][1]=0; acc[i][j][2]=0; acc[i][j][3]=0;
        }

    int kk = tid & 15, msi = tid >> 4;     // staging indices
    float fsum[8];                         // per-row partial F sums (register)
    #pragma unroll
    for (int p = 0; p < 8; p++) fsum[p] = 0.f;

    for (int k0 = kc*HKC; k0 < kc*HKC + HKC; k0 += 16) {
        #pragma unroll
        for (int p = 0; p < 8; p++) {
            int m = msi + p*16;
            size_t off = (rowbase + m)*SS + k0 + kk;
            float f = fuse1(Ms[off], Mc[off], Mp[off],
                            irs_a[m], irs_c[m], irs_p[m],
                            unitw, w0, w1, w2, fb);
            As[kk][m] = to_tf32(f);
            fsum[p] += f;
        }
        #pragma unroll
        for (int p = 0; p < 4; p++)
            Bs[kk][msi + p*16] = to_tf32(Bg[(size_t)(msi + p*16)*SS + k0 + kk]);
        __syncthreads();
        #pragma unroll
        for (int ks = 0; ks < 2; ks++) {
            int kb = ks * 8;
            uint32_t af[2][4], bf[4][2];
            #pragma unroll
            for (int mi = 0; mi < 2; mi++) {
                int mb = wr*32 + mi*16 + group;
                af[mi][0] = __float_as_uint(As[kb+tig  ][mb]);
                af[mi][1] = __float_as_uint(As[kb+tig  ][mb+8]);
                af[mi][2] = __float_as_uint(As[kb+tig+4][mb]);
                af[mi][3] = __float_as_uint(As[kb+tig+4][mb+8]);
            }
            #pragma unroll
            for (int nj = 0; nj < 4; nj++) {
                int nb = wc*32 + nj*8 + group;
                bf[nj][0] = __float_as_uint(Bs[kb+tig  ][nb]);
                bf[nj][1] = __float_as_uint(Bs[kb+tig+4][nb]);
            }
            #pragma unroll
            for (int mi = 0; mi < 2; mi++)
                #pragma unroll
                for (int nj = 0; nj < 4; nj++)
                    mma_tf32(acc[mi][nj], af[mi][0], af[mi][1], af[mi][2], af[mi][3],
                             bf[nj][0], bf[nj][1]);
        }
        __syncthreads();
    }

    // F rowsum reduction: lanes 0-15 / 16-31 each share one msi.
    // xor offsets 1,2,4,8 reduce within each 16-lane group independently.
    #pragma unroll
    for (int p = 0; p < 8; p++) {
        float v = fsum[p];
        v += __shfl_xor_sync(0xffffffffu, v, 1);
        v += __shfl_xor_sync(0xffffffffu, v, 2);
        v += __shfl_xor_sync(0xffffffffu, v, 4);
        v += __shfl_xor_sync(0xffffffffu, v, 8);
        if (kk == 0)
            atomicAdd(&g_frs[(size_t)hop*NTOK + rowbase + msi + p*16], v);
    }

    #pragma unroll
    for (int mi = 0; mi < 2; mi++)
        #pragma unroll
        for (int nj = 0; nj < 4; nj++) {
            int row = m0 + wr*32 + mi*16 + group;
            int col = wc*32 + nj*8 + 2*tig;
            atomicAdd(&Hg[(size_t)row*DD + col],     acc[mi][nj][0]);
            atomicAdd(&Hg[(size_t)row*DD + col + 1], acc[mi][nj][1]);
            atomicAdd(&Hg[(size_t)(row+8)*DD + col],     acc[mi][nj][2]);
            atomicAdd(&Hg[(size_t)(row+8)*DD + col + 1], acc[mi][nj][3]);
        }
}

// ---------------- 9) out = (gate-combined H) @ out_W^T ----------------
__global__ __launch_bounds__(256) void outproj_kernel(
    const float* __restrict__ outW, float* __restrict__ out)
{
    __shared__ float cs[16][65];
    __shared__ float ws[128][65];
    int tb = blockIdx.x * 16;
    int tid = threadIdx.x;
    #pragma unroll
    for (int e = tid; e < 16*64; e += 256) {
        int tl = e >> 6, ee = e & 63;
        int tok = tb + tl;
        float s0 = __fdividef(g_gate[tok*2+0], g_frs[tok] + EPSV);
        float s1 = __fdividef(g_gate[tok*2+1], g_frs[NTOK + tok] + EPSV);
        cs[tl][ee] = s0*g_H[(size_t)tok*DD + ee]
                   + s1*g_H[(size_t)NTOK*DD + (size_t)tok*DD + ee];
    }
    int tk2 = tid >> 5;
    int h4  = tid & 31;
    for (int hc = 0; hc < 4; hc++) {
        __syncthreads();
        #pragma unroll
        for (int e = tid; e < 128*64; e += 256)
            ws[e>>6][e&63] = outW[(size_t)hc*128*DD + e];
        __syncthreads();
        float a0[4] = {0,0,0,0}, a1[4] = {0,0,0,0};
        #pragma unroll 4
        for (int d = 0; d < 64; d++) {
            float c0 = cs[2*tk2][d], c1 = cs[2*tk2+1][d];
            #pragma unroll
            for (int j = 0; j < 4; j++) {
                float w = ws[h4*4 + j][d];
                a0[j] += c0*w; a1[j] += c1*w;
            }
        }
        *(float4*)&out[(size_t)(tb + 2*tk2)*HID + hc*128 + h4*4] =
            make_float4(a0[0], a0[1], a0[2], a0[3]);
        *(float4*)&out[(size_t)(tb + 2*tk2 + 1)*HID + hc*128 + h4*4] =
            make_float4(a1[0], a1[1], a1[2], a1[3]);
    }
}

// ---------------- launch ----------------
extern "C" void kernel_launch(void* const* d_in, const int* in_sizes, int n_in,
                              void* d_out, int out_size)
{
    const float* x      = (const float*)d_in[0];
    const float* Wq     = (const float*)d_in[1];
    const float* Wk     = (const float*)d_in[2];
    const float* Wv     = (const float*)d_in[3];
    const float* btab   = (const float*)d_in[4];
    const float* fw     = (const float*)d_in[5];
    const float* fbias  = (const float*)d_in[6];
    const float* hopW   = (const float*)d_in[7];
    const float* gateW  = (const float*)d_in[8];
    const float* gateb  = (const float*)d_in[9];
    const float* outW   = (const float*)d_in[10];
    const float* temp   = (const float*)d_in[11];
    const int*   relidx = (const int*)d_in[12];
    float* out = (float*)d_out;

    cudaFuncSetAttribute(gemm_bf16_kernel,
                         cudaFuncAttributeMaxDynamicSharedMemorySize, GEMM_DSMEM);

    zero_kernel<<<ZERO_BLOCKS, 256>>>();
    proj_kernel<<<NTOK/TOK_PB, 256>>>(x, Wq, Wk, Wv, gateW);
    rope_kernel<<<(NTOK*32)/256, 256>>>();
    hopv_gate_kernel<<<dim3(NTOK/64, 4), 256>>>(hopW, gateb);
    scores_kernel<<<dim3(16,16,NB), 256>>>(btab, relidx, temp);
    softmax_kernel<<<NTOK, 256>>>();
    transpose_kernel<<<dim3(32,32,NB), 256>>>();

    // hmat: 0=Ah 1=Th 2=Ph 3=Qmh ; mat: 1=P 2=Qm 3=A2 4=P2 5=Q2
    gemm_bf16_kernel<<<dim3(36,1,NB), 256, GEMM_DSMEM>>>(0,0,1, 2, 1); // P  = Ah Ah^T (tri)
    gemm_bf16_kernel<<<dim3(36,1,NB), 256, GEMM_DSMEM>>>(1,1,2, 3, 1); // Qm = Th Th^T (tri)
    gemm_bf16_kernel<<<dim3(64,1,NB), 256, GEMM_DSMEM>>>(0,1,3,-1, 0); // A2 = Ah Th^T (full)
    mirror2_kernel<<<dim3(28,32,NB), 256>>>(1, 2, 2, 3);               // P(+Ph), Qm(+Qmh)
    gemm_bf16_kernel<<<dim3(36,1,NB), 256, GEMM_DSMEM>>>(2,2,4,-1, 1); // P2 = Ph Ph^T (tri)
    gemm_bf16_kernel<<<dim3(36,1,NB), 256, GEMM_DSMEM>>>(3,3,5,-1, 1); // Q2 = Qmh Qmh^T (tri)
    mirror2_kernel<<<dim3(28,32,NB), 256>>>(4, -1, 5, -1);             // P2, Q2

    fused_hop_gemm_kernel<<<dim3(8, NB, HKS*2), 256>>>(fw, fbias);
    outproj_kernel<<<NTOK/16, 256>>>(outW, out);
}

// round 16
// speedup vs baseline: 1.1998x; 1.0582x over previous
#include <cuda_runtime.h>
#include <cuda_bf16.h>
#include <cstdint>

#define NB 8
#define SS 1024
#define DD 64
#define HID 512
#define NTOK (NB*SS)          // 8192
#define EPSV 1e-6f

// ---------------- device scratch (no allocation allowed) ----------------
__device__ float g_Q[NTOK*DD];
__device__ float g_K[NTOK*DD];
__device__ float g_V[NTOK*DD];
__device__ float g_gate[NTOK*2];
__device__ float g_rs[6*NTOK];           // rowsums: slots 1..5 = P,Qm,A2,P2,Q2
__device__ float g_frs[2*NTOK];          // rowsums of fused matrices
__device__ float g_H[2*NTOK*DD];         // hop outputs (pre-norm, atomic)
__device__ float g_A [(size_t)NB*SS*SS]; // softmax attention
__device__ float g_P [(size_t)NB*SS*SS]; // A A^T
__device__ float g_Qm[(size_t)NB*SS*SS]; // A^T A
__device__ float g_A2[(size_t)NB*SS*SS]; // A A
__device__ float g_P2[(size_t)NB*SS*SS]; // P P
__device__ float g_Q2[(size_t)NB*SS*SS]; // Qm Qm
__device__ float g_F [2*(size_t)NB*SS*SS]; // fused matrices fp32
__device__ float g_hopvT[2*(size_t)NB*DD*SS]; // hopv transposed, k-major, fp32
// bf16 GEMM operands
__device__ __nv_bfloat16 g_Ah [(size_t)NB*SS*SS];
__device__ __nv_bfloat16 g_Th [(size_t)NB*SS*SS];
__device__ __nv_bfloat16 g_Ph [(size_t)NB*SS*SS];
__device__ __nv_bfloat16 g_Qmh[(size_t)NB*SS*SS];

__device__ __forceinline__ float* matsel(int s) {
    switch (s) {
        case 0: return g_A;
        case 1: return g_P;
        case 2: return g_Qm;
        case 3: return g_A2;
        case 4: return g_P2;
        default: return g_Q2;
    }
}
__device__ __forceinline__ __nv_bfloat16* hmatsel(int s) {
    switch (s) {
        case 0: return g_Ah;
        case 1: return g_Th;
        case 2: return g_Ph;
        default: return g_Qmh;
    }
}

__device__ __forceinline__ float warp_max(float v) {
    #pragma unroll
    for (int o = 16; o > 0; o >>= 1) v = fmaxf(v, __shfl_xor_sync(0xffffffffu, v, o));
    return v;
}
__device__ __forceinline__ float warp_sum(float v) {
    #pragma unroll
    for (int o = 16; o > 0; o >>= 1) v += __shfl_xor_sync(0xffffffffu, v, o);
    return v;
}

// ---------------- 0) zero g_rs + g_H ----------------
#define ZTOT ((6*NTOK + 2*NTOK*DD)/4)
__global__ void zero_kernel()
{
    int gid = blockIdx.x*256 + threadIdx.x;   // float4 index
    if (gid >= ZTOT) return;
    if (gid < 6*NTOK/4)
        ((float4*)g_rs)[gid] = make_float4(0.f,0.f,0.f,0.f);
    else
        ((float4*)g_H)[gid - 6*NTOK/4] = make_float4(0.f,0.f,0.f,0.f);
}
#define ZERO_BLOCKS ((ZTOT + 255)/256)

// ---------------- 1) QKV + gate-logit projection ----------------
#define TOK_PB 16
__global__ __launch_bounds__(256) void proj_kernel(
    const float* __restrict__ x, const float* __restrict__ Wq,
    const float* __restrict__ Wk, const float* __restrict__ Wv,
    const float* __restrict__ gW)
{
    __shared__ float xs[TOK_PB*HID];
    int tb = blockIdx.x * TOK_PB;
    int tid = threadIdx.x;
    const float4* xg = (const float4*)(x + (size_t)tb*HID);
    float4* xs4 = (float4*)xs;
    #pragma unroll
    for (int i = tid; i < TOK_PB*HID/4; i += 256) xs4[i] = xg[i];
    __syncthreads();

    for (int o = tid; o < TOK_PB*194; o += 256) {
        int tok = o / 194, ch = o % 194;
        const float* w;
        if (ch < 64)       w = Wq + ch*HID;
        else if (ch < 128) w = Wk + (ch-64)*HID;
        else if (ch < 192) w = Wv + (ch-128)*HID;
        else               w = gW + (ch-192)*HID;
        const float4* w4  = (const float4*)w;
        const float4* xv4 = (const float4*)(xs + tok*HID);
        float acc = 0.f;
        #pragma unroll 8
        for (int k = 0; k < HID/4; k++) {
            float4 a = xv4[k];
            float4 b = __ldg(&w4[k]);
            acc += a.x*b.x + a.y*b.y + a.z*b.z + a.w*b.w;
        }
        size_t gt = tb + tok;
        if (ch < 64)       g_Q[gt*DD + ch]        = acc;
        else if (ch < 128) g_K[gt*DD + (ch-64)]   = acc;
        else if (ch < 192) g_V[gt*DD + (ch-128)]  = acc;
        else               g_gate[gt*2 + (ch-192)] = acc;
    }
}

// ---------------- 2) RoPE in place on Q,K ----------------
__global__ void rope_kernel()
{
    int gid = blockIdx.x*256 + threadIdx.x;
    if (gid >= NTOK*32) return;
    int tok = gid >> 5, j = gid & 31;
    int s = tok & (SS-1);
    float invf = (float)exp(-log(10000.0) * (double)j / 32.0);
    float ang = (float)s * invf;
    float sn, cs;
    sincosf(ang, &sn, &cs);
    size_t base = (size_t)tok * DD;
    float q0 = g_Q[base+j], q1 = g_Q[base+j+32];
    g_Q[base+j]    = q0*cs - q1*sn;
    g_Q[base+j+32] = q1*cs + q0*sn;
    float k0 = g_K[base+j], k1 = g_K[base+j+32];
    g_K[base+j]    = k0*cs - k1*sn;
    g_K[base+j+32] = k1*cs + k0*sn;
}

// ---------------- 3) hopvT (coalesced, e-split) ; gate softmax ----------------
__global__ __launch_bounds__(256) void hopv_gate_kernel(
    const float* __restrict__ hopW, const float* __restrict__ gateb)
{
    __shared__ float vs[64][65];
    int t0tok = blockIdx.x * 64;
    int eq = blockIdx.y;                       // e quarter 0..3
    int b = t0tok >> 10, s0 = t0tok & (SS-1);
    int tid = threadIdx.x;

    #pragma unroll
    for (int i = tid; i < 64*16; i += 256) {   // float4 granules
        int tokL = i >> 4;
        int d4 = (i & 15) * 4;
        float4 v = *(const float4*)(g_V + (size_t)(t0tok + tokL)*DD + d4);
        vs[tokL][d4] = v.x; vs[tokL][d4+1] = v.y;
        vs[tokL][d4+2] = v.z; vs[tokL][d4+3] = v.w;
    }
    __syncthreads();

    int tokL = tid & 63;
    int e0 = eq*16 + (tid >> 6);               // 4 e per block-thread-group
    int s = s0 + tokL;
    #pragma unroll 4
    for (int e = e0; e < eq*16 + 16; e += 4) {
        const float* w0 = hopW + e*DD;
        const float* w1 = hopW + DD*DD + e*DD;
        float a0 = 0.f, a1 = 0.f;
        #pragma unroll
        for (int d = 0; d < DD; d++) {
            float v = vs[tokL][d];
            a0 += v * __ldg(&w0[d]);
            a1 += v * __ldg(&w1[d]);
        }
        g_hopvT[((size_t)b*DD + e)*SS + s] = a0;
        g_hopvT[((size_t)(NB + b)*DD + e)*SS + s] = a1;
    }

    if (eq == 0 && tid < 64) {
        int tok = t0tok + tid;
        float l0 = g_gate[tok*2]   + __ldg(&gateb[0]);
        float l1 = g_gate[tok*2+1] + __ldg(&gateb[1]);
        float m = fmaxf(l0, l1);
        float e0v = __expf(l0-m), e1v = __expf(l1-m);
        float inv = 1.f/(e0v+e1v);
        g_gate[tok*2]   = e0v*inv;
        g_gate[tok*2+1] = e1v*inv;
    }
}

// ---------------- 4) scores ----------------
__global__ __launch_bounds__(256) void scores_kernel(
    const float* __restrict__ bias_table, const int* __restrict__ rel_idx,
    const float* __restrict__ temperature)
{
    __shared__ float qs[64][65];
    __shared__ float ks[64][65];
    int b = blockIdx.z;
    int s0 = blockIdx.y * 64, t0 = blockIdx.x * 64;
    int tid = threadIdx.x;
    const float* Qb = g_Q + ((size_t)b*SS + s0)*DD;
    const float* Kb = g_K + ((size_t)b*SS + t0)*DD;
    #pragma unroll
    for (int e = tid; e < 64*64; e += 256) {
        qs[e>>6][e&63] = Qb[e];
        ks[e>>6][e&63] = Kb[e];
    }
    __syncthreads();
    int ty = tid >> 4, tx = tid & 15;
    float c[4][4];
    #pragma unroll
    for (int i=0;i<4;i++) { c[i][0]=0;c[i][1]=0;c[i][2]=0;c[i][3]=0; }
    #pragma unroll 4
    for (int d = 0; d < 64; d++) {
        float rq[4], rk[4];
        #pragma unroll
        for (int i=0;i<4;i++) { rq[i] = qs[ty*4+i][d]; rk[i] = ks[tx*4+i][d]; }
        #pragma unroll
        for (int i=0;i<4;i++)
            #pragma unroll
            for (int j=0;j<4;j++) c[i][j] += rq[i]*rk[j];
    }
    float inv_t = 1.f / fmaxf(temperature[0], 0.1f);
    const float scale = 0.125f;
    float* Ab = g_A + (size_t)b*SS*SS;
    #pragma unroll
    for (int i = 0; i < 4; i++) {
        int s = s0 + ty*4 + i;
        int4 idx = *(const int4*)(rel_idx + (size_t)s*SS + t0 + tx*4);
        float4 out;
        out.x = (c[i][0]*scale + __ldg(&bias_table[idx.x])) * inv_t;
        out.y = (c[i][1]*scale + __ldg(&bias_table[idx.y])) * inv_t;
        out.z = (c[i][2]*scale + __ldg(&bias_table[idx.z])) * inv_t;
        out.w = (c[i][3]*scale + __ldg(&bias_table[idx.w])) * inv_t;
        *(float4*)(Ab + (size_t)s*SS + t0 + tx*4) = out;
    }
}

// ---------------- 5) row softmax in place on g_A (+ bf16 copy) ----------------
__global__ __launch_bounds__(256) void softmax_kernel()
{
    size_t row = blockIdx.x;
    float* Ar = g_A + row*SS;
    __nv_bfloat16* Ah = g_Ah + row*SS;
    int tid = threadIdx.x;
    int wid = tid >> 5, lane = tid & 31;
    __shared__ float sm[8];
    float4 v = ((float4*)Ar)[tid];
    float m = fmaxf(fmaxf(v.x, v.y), fmaxf(v.z, v.w));
    m = warp_max(m);
    if (lane == 0) sm[wid] = m;
    __syncthreads();
    if (wid == 0) {
        float t = (lane < 8) ? sm[lane] : -3.4e38f;
        t = warp_max(t);
        if (lane == 0) sm[0] = t;
    }
    __syncthreads();
    m = sm[0];
    __syncthreads();
    float e0 = __expf(v.x-m), e1 = __expf(v.y-m), e2 = __expf(v.z-m), e3 = __expf(v.w-m);
    float s = e0+e1+e2+e3;
    s = warp_sum(s);
    if (lane == 0) sm[wid] = s;
    __syncthreads();
    if (wid == 0) {
        float t = (lane < 8) ? sm[lane] : 0.f;
        t = warp_sum(t);
        if (lane == 0) sm[0] = t;
    }
    __syncthreads();
    float inv = 1.f / sm[0];
    float4 o = make_float4(e0*inv, e1*inv, e2*inv, e3*inv);
    ((float4*)Ar)[tid] = o;
    __nv_bfloat162 h0 = __floats2bfloat162_rn(o.x, o.y);
    __nv_bfloat162 h1 = __floats2bfloat162_rn(o.z, o.w);
    ((__nv_bfloat162*)Ah)[tid*2]   = h0;
    ((__nv_bfloat162*)Ah)[tid*2+1] = h1;
}

// ---------------- 5b) transpose: g_Th = (g_Ah)^T per batch (bf16 in/out) ----------------
__global__ __launch_bounds__(256) void transpose_kernel()
{
    __shared__ __nv_bfloat16 t[32][34];
    int b = blockIdx.z;
    int x0 = blockIdx.x*32, y0 = blockIdx.y*32;
    const __nv_bfloat16* Ab = g_Ah + (size_t)b*SS*SS;
    __nv_bfloat16* Tb = g_Th + (size_t)b*SS*SS;
    int tx = threadIdx.x & 31, ty = threadIdx.x >> 5;   // 32 x 8
    #pragma unroll
    for (int i = 0; i < 32; i += 8)
        t[ty+i][tx] = Ab[(size_t)(y0+ty+i)*SS + x0+tx];
    __syncthreads();
    #pragma unroll
    for (int i = 0; i < 32; i += 8)
        Tb[(size_t)(x0+ty+i)*SS + y0+tx] = t[tx][ty+i];
}

// ================= bf16 mma.sync batched NT GEMM (+rowsum epilogue) =================
__device__ __forceinline__ uint32_t s2u(const void* p) {
    uint32_t a;
    asm("{ .reg .u64 t; cvta.to.shared.u64 t, %1; cvt.u32.u64 %0, t; }" : "=r"(a) : "l"(p));
    return a;
}
#define SWZ(o) ((o) ^ (((o)>>3)&0x70))

__device__ __forceinline__ void cp16(uint32_t dst, const void* src) {
    asm volatile("cp.async.cg.shared.global [%0], [%1], 16;" :: "r"(dst), "l"(src));
}
__device__ __forceinline__ void cp_commit() { asm volatile("cp.async.commit_group;" ::: "memory"); }
#define CP_WAIT(n) asm volatile("cp.async.wait_group %0;" :: "n"(n) : "memory")

__device__ __forceinline__ void ldsm4(uint32_t* r, uint32_t addr) {
    asm volatile("ldmatrix.sync.aligned.m8n8.x4.shared.b16 {%0,%1,%2,%3}, [%4];"
        : "=r"(r[0]), "=r"(r[1]), "=r"(r[2]), "=r"(r[3]) : "r"(addr));
}
__device__ __forceinline__ void mma_bf16(float* c, const uint32_t* a,
                                         uint32_t b0, uint32_t b1) {
    asm volatile(
        "mma.sync.aligned.m16n8k16.row.col.f32.bf16.bf16.f32 "
        "{%0,%1,%2,%3},{%4,%5,%6,%7},{%8,%9},{%0,%1,%2,%3};"
        : "+f"(c[0]), "+f"(c[1]), "+f"(c[2]), "+f"(c[3])
        : "r"(a[0]), "r"(a[1]), "r"(a[2]), "r"(a[3]), "r"(b0), "r"(b1));
}

#define STG 3
#define CK 64                        // k per chunk (bf16): 128B per row
#define NCH (SS/CK)                  // 16
#define STAGE_BYTES 32768
#define GEMM_DSMEM (STG*STAGE_BYTES) // 98304

__global__ __launch_bounds__(256, 2)
void gemm_bf16_kernel(int asel, int bsel, int cfsel, int chsel, int tri)
{
    extern __shared__ __align__(16) char dsmem[];
    uint32_t sb = s2u(dsmem);
    int tid = threadIdx.x;
    int warp = tid >> 5, lane = tid & 31;

    size_t off = (size_t)blockIdx.z*SS*SS;
    const __nv_bfloat16* Ag = hmatsel(asel) + off;
    const __nv_bfloat16* Bg = hmatsel(bsel) + off;
    float* Cg = matsel(cfsel) + off;
    __nv_bfloat16* Chg = (chsel >= 0) ? hmatsel(chsel) + off : nullptr;

    int bi, bj;
    if (tri) {
        int t = blockIdx.x, i = 0;
        while (t >= 8 - i) { t -= 8 - i; i++; }
        bi = i; bj = i + t;
    } else {
        bi = blockIdx.x >> 3; bj = blockIdx.x & 7;
    }
    int m0 = bi*128, n0 = bj*128;
    bool same = (tri != 0) && (bi == bj) && (asel == bsel);
    uint32_t bBase = same ? 0u : 16384u;

    int wm = (warp >> 2)*64, wn = (warp & 3)*32;
    int rlane = (lane & 7) + ((lane >> 3) & 1)*8;
    int clane = (lane >> 4) & 1;

    float acc[4][4][4];
    #pragma unroll
    for (int i = 0; i < 4; i++)
        #pragma unroll
        for (int j = 0; j < 4; j++) {
            acc[i][j][0]=0; acc[i][j][1]=0; acc[i][j][2]=0; acc[i][j][3]=0;
        }

    auto load_chunk = [&](int c) {
        uint32_t stg = sb + (uint32_t)(c % STG) * STAGE_BYTES;
        int k0 = c * CK;
        #pragma unroll
        for (int it = 0; it < 8; it++) {
            int u = tid + it*256;
            int r = u >> 3;
            int ch = u & 7;
            if (r < 128) {
                const __nv_bfloat16* gsrc = Ag + (size_t)(m0 + r)*SS + k0 + ch*8;
                cp16(stg + SWZ((uint32_t)(r*128 + ch*16)), gsrc);
            } else if (!same) {
                const __nv_bfloat16* gsrc = Bg + (size_t)(n0 + (r-128))*SS + k0 + ch*8;
                cp16(stg + 16384u + SWZ((uint32_t)((r-128)*128 + ch*16)), gsrc);
            }
        }
    };

    for (int c = 0; c < STG-1; c++) { load_chunk(c); cp_commit(); }

    for (int c = 0; c < NCH; c++) {
        int lc = c + STG - 1;
        if (lc < NCH) load_chunk(lc);
        cp_commit();
        CP_WAIT(STG-1);
        __syncthreads();
        uint32_t stg = sb + (uint32_t)(c % STG) * STAGE_BYTES;
        #pragma unroll
        for (int ks = 0; ks < CK/16; ks++) {
            uint32_t af[4][4], bfr[2][4];
            int kch = ks*2 + clane;
            #pragma unroll
            for (int mi = 0; mi < 4; mi++) {
                int r = wm + mi*16 + rlane;
                ldsm4(af[mi], stg + SWZ((uint32_t)(r*128 + kch*16)));
            }
            #pragma unroll
            for (int nt = 0; nt < 2; nt++) {
                int r = wn + nt*16 + rlane;
                ldsm4(bfr[nt], stg + bBase + SWZ((uint32_t)(r*128 + kch*16)));
            }
            #pragma unroll
            for (int mi = 0; mi < 4; mi++)
                #pragma unroll
                for (int nj = 0; nj < 4; nj++) {
                    int nt = nj >> 1, sel = nj & 1;
                    mma_bf16(acc[mi][nj], af[mi], bfr[nt][sel], bfr[nt][sel+2]);
                }
        }
        __syncthreads();
    }

    int rr = lane >> 2, cc2 = (lane & 3)*2;
    #pragma unroll
    for (int mi = 0; mi < 4; mi++) {
        #pragma unroll
        for (int nj = 0; nj < 4; nj++) {
            int row = m0 + wm + mi*16 + rr;
            int col = n0 + wn + nj*8 + cc2;
            float2 v01 = make_float2(acc[mi][nj][0], acc[mi][nj][1]);
            float2 v23 = make_float2(acc[mi][nj][2], acc[mi][nj][3]);
            *(float2*)&Cg[(size_t)row*SS + col]     = v01;
            *(float2*)&Cg[(size_t)(row+8)*SS + col] = v23;
            if (Chg) {
                *(__nv_bfloat162*)&Chg[(size_t)row*SS + col] =
                    __floats2bfloat162_rn(v01.x, v01.y);
                *(__nv_bfloat162*)&Chg[(size_t)(row+8)*SS + col] =
                    __floats2bfloat162_rn(v23.x, v23.y);
            }
        }
    }

    // ---- rowsum epilogue: slot index == cfsel ----
    float* rs = g_rs + (size_t)cfsel*NTOK + (size_t)blockIdx.z*SS;
    #pragma unroll
    for (int mi = 0; mi < 4; mi++) {
        float r0 = 0.f, r1 = 0.f;
        #pragma unroll
        for (int nj = 0; nj < 4; nj++) {
            r0 += acc[mi][nj][0] + acc[mi][nj][1];
            r1 += acc[mi][nj][2] + acc[mi][nj][3];
        }
        r0 += __shfl_xor_sync(0xffffffffu, r0, 1);
        r0 += __shfl_xor_sync(0xffffffffu, r0, 2);
        r1 += __shfl_xor_sync(0xffffffffu, r1, 1);
        r1 += __shfl_xor_sync(0xffffffffu, r1, 2);
        if ((lane & 3) == 0) {
            int row = m0 + wm + mi*16 + rr;
            atomicAdd(&rs[row], r0);
            atomicAdd(&rs[row+8], r1);
        }
    }
    if (tri && bi != bj) {
        #pragma unroll
        for (int nj = 0; nj < 4; nj++) {
            float c0 = 0.f, c1 = 0.f;
            #pragma unroll
            for (int mi = 0; mi < 4; mi++) {
                c0 += acc[mi][nj][0] + acc[mi][nj][2];
                c1 += acc[mi][nj][1] + acc[mi][nj][3];
            }
            c0 += __shfl_xor_sync(0xffffffffu, c0, 4);
            c0 += __shfl_xor_sync(0xffffffffu, c0, 8);
            c0 += __shfl_xor_sync(0xffffffffu, c0, 16);
            c1 += __shfl_xor_sync(0xffffffffu, c1, 4);
            c1 += __shfl_xor_sync(0xffffffffu, c1, 8);
            c1 += __shfl_xor_sync(0xffffffffu, c1, 16);
            if (lane < 4) {
                int col = n0 + wn + nj*8 + cc2;
                atomicAdd(&rs[col], c0);
                atomicAdd(&rs[col+1], c1);
            }
        }
    }
}

// ---------------- 6b) mirror lower triangle of two symmetric matrices ----------------
__global__ __launch_bounds__(256) void mirror2_kernel(
    int m0sel, int h0sel, int m1sel, int h1sel)
{
    __shared__ float t[32][33];
    size_t off = (size_t)blockIdx.z*SS*SS;
    int which = blockIdx.y >> 4;
    int msel = which ? m1sel : m0sel;
    int hsel = which ? h1sel : h0sel;
    float* M = matsel(msel) + off;
    __nv_bfloat16* Mh = (hsel >= 0) ? hmatsel(hsel) + off : nullptr;

    int p = blockIdx.x, i = 0;
    while (p >= 7 - i) { p -= 7 - i; i++; }
    int j = i + 1 + p;
    int sub = blockIdx.y & 15;
    int y0 = i*128 + (sub >> 2)*32;
    int x0 = j*128 + (sub & 3)*32;
    int tx = threadIdx.x & 31, ty = threadIdx.x >> 5;
    #pragma unroll
    for (int k = 0; k < 32; k += 8)
        t[ty+k][tx] = M[(size_t)(y0+ty+k)*SS + x0+tx];
    __syncthreads();
    #pragma unroll
    for (int k = 0; k < 32; k += 8) {
        float v = t[tx][ty+k];
        size_t dst = (size_t)(x0+ty+k)*SS + y0+tx;
        M[dst] = v;
        if (Mh) Mh[dst] = __float2bfloat16(v);
    }
}

// ---------------- 8a) fused matrices: single pass, rowsums from g_rs ----------------
__device__ __forceinline__ float fuse1(float a, float b, float c,
                                       float ia, float ib, float ic,
                                       bool unitw, float w0, float w1, float w2, float fb)
{
    float ps = fminf(fmaxf(a*ia, EPSV), 1.f-EPSV);
    float pc = fminf(fmaxf(b*ib, EPSV), 1.f-EPSV);
    float pp = fminf(fmaxf(c*ic, EPSV), 1.f-EPSV);
    if (unitw) {
        float num = ps*pc*pp;
        float den = (1.f-ps+EPSV)*(1.f-pc+EPSV)*(1.f-pp+EPSV);
        return __fdividef(num, num + den);
    }
    float L0 = __logf(__fdividef(ps, 1.f-ps+EPSV));
    float L1 = __logf(__fdividef(pc, 1.f-pc+EPSV));
    float L2 = __logf(__fdividef(pp, 1.f-pp+EPSV));
    float logit = fb + w0*L0 + w1*L1 + w2*L2;
    return __fdividef(1.f, 1.f+__expf(-logit));
}

__global__ __launch_bounds__(256) void fusedmat_kernel(
    const float* __restrict__ fusion_w, const float* __restrict__ fusion_b)
{
    __shared__ float irs_s[16], irs_c[16], irs_p[16];
    int hop = blockIdx.z, b = blockIdx.y, sr0 = blockIdx.x*16;
    int tid = threadIdx.x;
    const float *Ms, *Mc, *Mp;
    if (hop == 0) { Ms = g_A;  Mc = g_P;  Mp = g_Qm; }
    else          { Ms = g_A2; Mc = g_P2; Mp = g_Q2; }
    float w0 = fusion_w[hop*3+0], w1 = fusion_w[hop*3+1], w2 = fusion_w[hop*3+2];
    float fb = fusion_b[hop];
    bool unitw = (w0 == 1.f) && (w1 == 1.f) && (w2 == 1.f) && (fb == 0.f);
    size_t rowbase = (size_t)b*SS + sr0;

    if (tid < 16) {
        if (hop == 0) irs_s[tid] = 1.f/(1.f + EPSV);   // softmax rows sum to 1
        else irs_s[tid] = 1.f/(g_rs[(size_t)3*NTOK + rowbase + tid] + EPSV);
        irs_c[tid] = 1.f/(g_rs[(size_t)(hop ? 4 : 1)*NTOK + rowbase + tid] + EPSV);
        irs_p[tid] = 1.f/(g_rs[(size_t)(hop ? 5 : 2)*NTOK + rowbase + tid] + EPSV);
    }
    __syncthreads();

    int r = tid >> 4, c16 = tid & 15;
    float ia = irs_s[r], ib = irs_c[r], ic = irs_p[r];
    size_t rowoff = (rowbase + r)*SS;
    float* Fr = g_F + (size_t)hop*NB*SS*SS + rowoff;
    float sum = 0.f;
    #pragma unroll
    for (int j = 0; j < 16; j++) {
        int col = c16*4 + j*64;
        float4 ms = *(const float4*)(Ms + rowoff + col);
        float4 mc = *(const float4*)(Mc + rowoff + col);
        float4 mp = *(const float4*)(Mp + rowoff + col);
        float4 f;
        f.x = fuse1(ms.x, mc.x, mp.x, ia, ib, ic, unitw, w0, w1, w2, fb);
        f.y = fuse1(ms.y, mc.y, mp.y, ia, ib, ic, unitw, w0, w1, w2, fb);
        f.z = fuse1(ms.z, mc.z, mp.z, ia, ib, ic, unitw, w0, w1, w2, fb);
        f.w = fuse1(ms.w, mc.w, mp.w, ia, ib, ic, unitw, w0, w1, w2, fb);
        sum += (f.x+f.y) + (f.z+f.w);
        *(float4*)(Fr + col) = f;
    }
    #pragma unroll
    for (int o = 8; o > 0; o >>= 1) sum += __shfl_xor_sync(0xffffffffu, sum, o);
    if (c16 == 0) g_frs[(size_t)hop*NTOK + rowbase + r] = sum;
}

// ---------------- 8b) H[hop] += F @ hopvT^T  (TF32 mma, split-K x4) ----------------
__device__ __forceinline__ float to_tf32(float x) {
    uint32_t u;
    asm("cvt.rna.tf32.f32 %0, %1;" : "=r"(u) : "f"(x));
    return __uint_as_float(u);
}
__device__ __forceinline__ void mma_tf32(float* c,
    uint32_t a0, uint32_t a1, uint32_t a2, uint32_t a3, uint32_t b0, uint32_t b1)
{
    asm volatile(
        "mma.sync.aligned.m16n8k8.row.col.f32.tf32.tf32.f32 "
        "{%0,%1,%2,%3},{%4,%5,%6,%7},{%8,%9},{%0,%1,%2,%3};"
        : "+f"(c[0]), "+f"(c[1]), "+f"(c[2]), "+f"(c[3])
        : "r"(a0), "r"(a1), "r"(a2), "r"(a3), "r"(b0), "r"(b1));
}

#define HKS 4                     // split-K factor
#define HKC (SS/HKS)              // 256 k per block

__global__ __launch_bounds__(256) void hop_gemm_kernel()
{
    __shared__ float As[16][132];   // [k][m]
    __shared__ float Bs[16][68];    // [k][n]
    int tid = threadIdx.x;
    int warp = tid >> 5, lane = tid & 31;
    int hop = blockIdx.z >> 2, kc = blockIdx.z & 3;
    int b = blockIdx.y, m0 = blockIdx.x*128;

    const float* Ag = g_F + (size_t)hop*NB*SS*SS + (size_t)b*SS*SS;
    const float* Bg = g_hopvT + (size_t)(hop*NB + b)*DD*SS;
    float* Hg = g_H + (size_t)hop*NTOK*DD + (size_t)b*SS*DD;

    int wr = warp >> 1, wc = warp & 1;     // 4 x 2 warps, tile 32(m) x 32(n)
    int group = lane >> 2, tig = lane & 3;

    float acc[2][4][4];
    #pragma unroll
    for (int i = 0; i < 2; i++)
        #pragma unroll
        for (int j = 0; j < 4; j++) {
            acc[i][j][0]=0; acc[i][j][1]=0; acc[i][j][2]=0; acc[i][j][3]=0;
        }

    int kk = tid & 15, msi = tid >> 4;     // staging indices
    for (int k0 = kc*HKC; k0 < kc*HKC + HKC; k0 += 16) {
        #pragma unroll
        for (int p = 0; p < 8; p++)
            As[kk][msi + p*16] = to_tf32(Ag[(size_t)(m0 + msi + p*16)*SS + k0 + kk]);
        #pragma unroll
        for (int p = 0; p < 4; p++)
            Bs[kk][msi + p*16] = to_tf32(Bg[(size_t)(msi + p*16)*SS + k0 + kk]);
        __syncthreads();
        #pragma unroll
        for (int ks = 0; ks < 2; ks++) {
            int kb = ks * 8;
            uint32_t af[2][4], bf[4][2];
            #pragma unroll
            for (int mi = 0; mi < 2; mi++) {
                int mb = wr*32 + mi*16 + group;
                af[mi][0] = __float_as_uint(As[kb+tig  ][mb]);
                af[mi][1] = __float_as_uint(As[kb+tig  ][mb+8]);
                af[mi][2] = __float_as_uint(As[kb+tig+4][mb]);
                af[mi][3] = __float_as_uint(As[kb+tig+4][mb+8]);
            }
            #pragma unroll
            for (int nj = 0; nj < 4; nj++) {
                int nb = wc*32 + nj*8 + group;
                bf[nj][0] = __float_as_uint(Bs[kb+tig  ][nb]);
                bf[nj][1] = __float_as_uint(Bs[kb+tig+4][nb]);
            }
            #pragma unroll
            for (int mi = 0; mi < 2; mi++)
                #pragma unroll
                for (int nj = 0; nj < 4; nj++)
                    mma_tf32(acc[mi][nj], af[mi][0], af[mi][1], af[mi][2], af[mi][3],
                             bf[nj][0], bf[nj][1]);
        }
        __syncthreads();
    }

    #pragma unroll
    for (int mi = 0; mi < 2; mi++)
        #pragma unroll
        for (int nj = 0; nj < 4; nj++) {
            int row = m0 + wr*32 + mi*16 + group;
            int col = wc*32 + nj*8 + 2*tig;
            atomicAdd(&Hg[(size_t)row*DD + col],     acc[mi][nj][0]);
            atomicAdd(&Hg[(size_t)row*DD + col + 1], acc[mi][nj][1]);
            atomicAdd(&Hg[(size_t)(row+8)*DD + col],     acc[mi][nj][2]);
            atomicAdd(&Hg[(size_t)(row+8)*DD + col + 1], acc[mi][nj][3]);
        }
}

// ---------------- 9) out = (gate-combined H) @ out_W^T ----------------
__global__ __launch_bounds__(256) void outproj_kernel(
    const float* __restrict__ outW, float* __restrict__ out)
{
    __shared__ float cs[16][65];
    __shared__ float ws[128][65];
    int tb = blockIdx.x * 16;
    int tid = threadIdx.x;
    #pragma unroll
    for (int e = tid; e < 16*64; e += 256) {
        int tl = e >> 6, ee = e & 63;
        int tok = tb + tl;
        float s0 = __fdividef(g_gate[tok*2+0], g_frs[tok] + EPSV);
        float s1 = __fdividef(g_gate[tok*2+1], g_frs[NTOK + tok] + EPSV);
        cs[tl][ee] = s0*g_H[(size_t)tok*DD + ee]
                   + s1*g_H[(size_t)NTOK*DD + (size_t)tok*DD + ee];
    }
    int tk2 = tid >> 5;
    int h4  = tid & 31;
    for (int hc = 0; hc < 4; hc++) {
        __syncthreads();
        #pragma unroll
        for (int e = tid; e < 128*64; e += 256)
            ws[e>>6][e&63] = outW[(size_t)hc*128*DD + e];
        __syncthreads();
        float a0[4] = {0,0,0,0}, a1[4] = {0,0,0,0};
        #pragma unroll 4
        for (int d = 0; d < 64; d++) {
            float c0 = cs[2*tk2][d], c1 = cs[2*tk2+1][d];
            #pragma unroll
            for (int j = 0; j < 4; j++) {
                float w = ws[h4*4 + j][d];
                a0[j] += c0*w; a1[j] += c1*w;
            }
        }
        *(float4*)&out[(size_t)(tb + 2*tk2)*HID + hc*128 + h4*4] =
            make_float4(a0[0], a0[1], a0[2], a0[3]);
        *(float4*)&out[(size_t)(tb + 2*tk2 + 1)*HID + hc*128 + h4*4] =
            make_float4(a1[0], a1[1], a1[2], a1[3]);
    }
}

// ---------------- launch ----------------
extern "C" void kernel_launch(void* const* d_in, const int* in_sizes, int n_in,
                              void* d_out, int out_size)
{
    const float* x      = (const float*)d_in[0];
    const float* Wq     = (const float*)d_in[1];
    const float* Wk     = (const float*)d_in[2];
    const float* Wv     = (const float*)d_in[3];
    const float* btab   = (const float*)d_in[4];
    const float* fw     = (const float*)d_in[5];
    const float* fbias  = (const float*)d_in[6];
    const float* hopW   = (const float*)d_in[7];
    const float* gateW  = (const float*)d_in[8];
    const float* gateb  = (const float*)d_in[9];
    const float* outW   = (const float*)d_in[10];
    const float* temp   = (const float*)d_in[11];
    const int*   relidx = (const int*)d_in[12];
    float* out = (float*)d_out;

    cudaFuncSetAttribute(gemm_bf16_kernel,
                         cudaFuncAttributeMaxDynamicSharedMemorySize, GEMM_DSMEM);

    zero_kernel<<<ZERO_BLOCKS, 256>>>();
    proj_kernel<<<NTOK/TOK_PB, 256>>>(x, Wq, Wk, Wv, gateW);
    rope_kernel<<<(NTOK*32)/256, 256>>>();
    hopv_gate_kernel<<<dim3(NTOK/64, 4), 256>>>(hopW, gateb);
    scores_kernel<<<dim3(16,16,NB), 256>>>(btab, relidx, temp);
    softmax_kernel<<<NTOK, 256>>>();
    transpose_kernel<<<dim3(32,32,NB), 256>>>();

    // hmat: 0=Ah 1=Th 2=Ph 3=Qmh ; mat: 1=P 2=Qm 3=A2 4=P2 5=Q2
    gemm_bf16_kernel<<<dim3(36,1,NB), 256, GEMM_DSMEM>>>(0,0,1, 2, 1); // P  = Ah Ah^T (tri)
    gemm_bf16_kernel<<<dim3(36,1,NB), 256, GEMM_DSMEM>>>(1,1,2, 3, 1); // Qm = Th Th^T (tri)
    gemm_bf16_kernel<<<dim3(64,1,NB), 256, GEMM_DSMEM>>>(0,1,3,-1, 0); // A2 = Ah Th^T (full)
    mirror2_kernel<<<dim3(28,32,NB), 256>>>(1, 2, 2, 3);               // P(+Ph), Qm(+Qmh)
    gemm_bf16_kernel<<<dim3(36,1,NB), 256, GEMM_DSMEM>>>(2,2,4,-1, 1); // P2 = Ph Ph^T (tri)
    gemm_bf16_kernel<<<dim3(36,1,NB), 256, GEMM_DSMEM>>>(3,3,5,-1, 1); // Q2 = Qmh Qmh^T (tri)
    mirror2_kernel<<<dim3(28,32,NB), 256>>>(4, -1, 5, -1);             // P2, Q2

    fusedmat_kernel<<<dim3(SS/16, NB, 2), 256>>>(fw, fbias);
    hop_gemm_kernel<<<dim3(8, NB, HKS*2), 256>>>();
    outproj_kernel<<<NTOK/16, 256>>>(outW, out);
}

// round 17
// speedup vs baseline: 1.2055x; 1.0047x over previous
#include <cuda_runtime.h>
#include <cuda_bf16.h>
#include <cstdint>

#define NB 8
#define SS 1024
#define DD 64
#define HID 512
#define NTOK (NB*SS)          // 8192
#define EPSV 1e-6f

// ---------------- device scratch (no allocation allowed) ----------------
__device__ float g_Q[NTOK*DD];
__device__ float g_K[NTOK*DD];
__device__ float g_V[NTOK*DD];
__device__ float g_gate[NTOK*2];
__device__ float g_rs[6*NTOK];           // rowsums: slots 1..5 = P,Qm,A2,P2,Q2
__device__ float g_frs[2*NTOK];          // rowsums of fused matrices
__device__ float g_H[2*NTOK*DD];         // hop outputs (pre-norm, atomic)
__device__ float g_A [(size_t)NB*SS*SS]; // softmax attention
__device__ float g_P [(size_t)NB*SS*SS]; // A A^T
__device__ float g_Qm[(size_t)NB*SS*SS]; // A^T A
__device__ float g_A2[(size_t)NB*SS*SS]; // A A
__device__ float g_P2[(size_t)NB*SS*SS]; // P P
__device__ float g_Q2[(size_t)NB*SS*SS]; // Qm Qm
__device__ float g_F [2*(size_t)NB*SS*SS]; // fused matrices fp32
__device__ float g_hopvT[2*(size_t)NB*DD*SS]; // hopv transposed, k-major, fp32
// bf16 GEMM operands
__device__ __nv_bfloat16 g_Ah [(size_t)NB*SS*SS];
__device__ __nv_bfloat16 g_Th [(size_t)NB*SS*SS];
__device__ __nv_bfloat16 g_Ph [(size_t)NB*SS*SS];
__device__ __nv_bfloat16 g_Qmh[(size_t)NB*SS*SS];

__device__ __forceinline__ float* matsel(int s) {
    switch (s) {
        case 0: return g_A;
        case 1: return g_P;
        case 2: return g_Qm;
        case 3: return g_A2;
        case 4: return g_P2;
        default: return g_Q2;
    }
}
__device__ __forceinline__ __nv_bfloat16* hmatsel(int s) {
    switch (s) {
        case 0: return g_Ah;
        case 1: return g_Th;
        case 2: return g_Ph;
        default: return g_Qmh;
    }
}

__device__ __forceinline__ float warp_max(float v) {
    #pragma unroll
    for (int o = 16; o > 0; o >>= 1) v = fmaxf(v, __shfl_xor_sync(0xffffffffu, v, o));
    return v;
}
__device__ __forceinline__ float warp_sum(float v) {
    #pragma unroll
    for (int o = 16; o > 0; o >>= 1) v += __shfl_xor_sync(0xffffffffu, v, o);
    return v;
}

// ---------------- 0) zero g_rs + g_H ----------------
#define ZTOT ((6*NTOK + 2*NTOK*DD)/4)
__global__ void zero_kernel()
{
    int gid = blockIdx.x*256 + threadIdx.x;   // float4 index
    if (gid >= ZTOT) return;
    if (gid < 6*NTOK/4)
        ((float4*)g_rs)[gid] = make_float4(0.f,0.f,0.f,0.f);
    else
        ((float4*)g_H)[gid - 6*NTOK/4] = make_float4(0.f,0.f,0.f,0.f);
}
#define ZERO_BLOCKS ((ZTOT + 255)/256)

// ---------------- 1) QKV + gate-logit projection ----------------
#define TOK_PB 16
__global__ __launch_bounds__(256) void proj_kernel(
    const float* __restrict__ x, const float* __restrict__ Wq,
    const float* __restrict__ Wk, const float* __restrict__ Wv,
    const float* __restrict__ gW)
{
    __shared__ float xs[TOK_PB*HID];
    int tb = blockIdx.x * TOK_PB;
    int tid = threadIdx.x;
    const float4* xg = (const float4*)(x + (size_t)tb*HID);
    float4* xs4 = (float4*)xs;
    #pragma unroll
    for (int i = tid; i < TOK_PB*HID/4; i += 256) xs4[i] = xg[i];
    __syncthreads();

    for (int o = tid; o < TOK_PB*194; o += 256) {
        int tok = o / 194, ch = o % 194;
        const float* w;
        if (ch < 64)       w = Wq + ch*HID;
        else if (ch < 128) w = Wk + (ch-64)*HID;
        else if (ch < 192) w = Wv + (ch-128)*HID;
        else               w = gW + (ch-192)*HID;
        const float4* w4  = (const float4*)w;
        const float4* xv4 = (const float4*)(xs + tok*HID);
        float acc = 0.f;
        #pragma unroll 8
        for (int k = 0; k < HID/4; k++) {
            float4 a = xv4[k];
            float4 b = __ldg(&w4[k]);
            acc += a.x*b.x + a.y*b.y + a.z*b.z + a.w*b.w;
        }
        size_t gt = tb + tok;
        if (ch < 64)       g_Q[gt*DD + ch]        = acc;
        else if (ch < 128) g_K[gt*DD + (ch-64)]   = acc;
        else if (ch < 192) g_V[gt*DD + (ch-128)]  = acc;
        else               g_gate[gt*2 + (ch-192)] = acc;
    }
}

// ---------------- 2) RoPE in place on Q,K ----------------
__global__ void rope_kernel()
{
    int gid = blockIdx.x*256 + threadIdx.x;
    if (gid >= NTOK*32) return;
    int tok = gid >> 5, j = gid & 31;
    int s = tok & (SS-1);
    float invf = (float)exp(-log(10000.0) * (double)j / 32.0);
    float ang = (float)s * invf;
    float sn, cs;
    sincosf(ang, &sn, &cs);
    size_t base = (size_t)tok * DD;
    float q0 = g_Q[base+j], q1 = g_Q[base+j+32];
    g_Q[base+j]    = q0*cs - q1*sn;
    g_Q[base+j+32] = q1*cs + q0*sn;
    float k0 = g_K[base+j], k1 = g_K[base+j+32];
    g_K[base+j]    = k0*cs - k1*sn;
    g_K[base+j+32] = k1*cs + k0*sn;
}

// ---------------- 3) hopvT (coalesced, e-split) ; gate softmax ----------------
__global__ __launch_bounds__(256) void hopv_gate_kernel(
    const float* __restrict__ hopW, const float* __restrict__ gateb)
{
    __shared__ float vs[64][65];
    int t0tok = blockIdx.x * 64;
    int eq = blockIdx.y;                       // e quarter 0..3
    int b = t0tok >> 10, s0 = t0tok & (SS-1);
    int tid = threadIdx.x;

    #pragma unroll
    for (int i = tid; i < 64*16; i += 256) {   // float4 granules
        int tokL = i >> 4;
        int d4 = (i & 15) * 4;
        float4 v = *(const float4*)(g_V + (size_t)(t0tok + tokL)*DD + d4);
        vs[tokL][d4] = v.x; vs[tokL][d4+1] = v.y;
        vs[tokL][d4+2] = v.z; vs[tokL][d4+3] = v.w;
    }
    __syncthreads();

    int tokL = tid & 63;
    int e0 = eq*16 + (tid >> 6);               // 4 e per block-thread-group
    int s = s0 + tokL;
    #pragma unroll 4
    for (int e = e0; e < eq*16 + 16; e += 4) {
        const float* w0 = hopW + e*DD;
        const float* w1 = hopW + DD*DD + e*DD;
        float a0 = 0.f, a1 = 0.f;
        #pragma unroll
        for (int d = 0; d < DD; d++) {
            float v = vs[tokL][d];
            a0 += v * __ldg(&w0[d]);
            a1 += v * __ldg(&w1[d]);
        }
        g_hopvT[((size_t)b*DD + e)*SS + s] = a0;
        g_hopvT[((size_t)(NB + b)*DD + e)*SS + s] = a1;
    }

    if (eq == 0 && tid < 64) {
        int tok = t0tok + tid;
        float l0 = g_gate[tok*2]   + __ldg(&gateb[0]);
        float l1 = g_gate[tok*2+1] + __ldg(&gateb[1]);
        float m = fmaxf(l0, l1);
        float e0v = __expf(l0-m), e1v = __expf(l1-m);
        float inv = 1.f/(e0v+e1v);
        g_gate[tok*2]   = e0v*inv;
        g_gate[tok*2+1] = e1v*inv;
    }
}

// ---------------- 4) scores ----------------
__global__ __launch_bounds__(256) void scores_kernel(
    const float* __restrict__ bias_table, const int* __restrict__ rel_idx,
    const float* __restrict__ temperature)
{
    __shared__ float qs[64][65];
    __shared__ float ks[64][65];
    int b = blockIdx.z;
    int s0 = blockIdx.y * 64, t0 = blockIdx.x * 64;
    int tid = threadIdx.x;
    const float* Qb = g_Q + ((size_t)b*SS + s0)*DD;
    const float* Kb = g_K + ((size_t)b*SS + t0)*DD;
    #pragma unroll
    for (int e = tid; e < 64*64; e += 256) {
        qs[e>>6][e&63] = Qb[e];
        ks[e>>6][e&63] = Kb[e];
    }
    __syncthreads();
    int ty = tid >> 4, tx = tid & 15;
    float c[4][4];
    #pragma unroll
    for (int i=0;i<4;i++) { c[i][0]=0;c[i][1]=0;c[i][2]=0;c[i][3]=0; }
    #pragma unroll 4
    for (int d = 0; d < 64; d++) {
        float rq[4], rk[4];
        #pragma unroll
        for (int i=0;i<4;i++) { rq[i] = qs[ty*4+i][d]; rk[i] = ks[tx*4+i][d]; }
        #pragma unroll
        for (int i=0;i<4;i++)
            #pragma unroll
            for (int j=0;j<4;j++) c[i][j] += rq[i]*rk[j];
    }
    float inv_t = 1.f / fmaxf(temperature[0], 0.1f);
    const float scale = 0.125f;
    float* Ab = g_A + (size_t)b*SS*SS;
    #pragma unroll
    for (int i = 0; i < 4; i++) {
        int s = s0 + ty*4 + i;
        int4 idx = *(const int4*)(rel_idx + (size_t)s*SS + t0 + tx*4);
        float4 out;
        out.x = (c[i][0]*scale + __ldg(&bias_table[idx.x])) * inv_t;
        out.y = (c[i][1]*scale + __ldg(&bias_table[idx.y])) * inv_t;
        out.z = (c[i][2]*scale + __ldg(&bias_table[idx.z])) * inv_t;
        out.w = (c[i][3]*scale + __ldg(&bias_table[idx.w])) * inv_t;
        *(float4*)(Ab + (size_t)s*SS + t0 + tx*4) = out;
    }
}

// ---------------- 5) row softmax in place on g_A (+ bf16 copy) ----------------
__global__ __launch_bounds__(256) void softmax_kernel()
{
    size_t row = blockIdx.x;
    float* Ar = g_A + row*SS;
    __nv_bfloat16* Ah = g_Ah + row*SS;
    int tid = threadIdx.x;
    int wid = tid >> 5, lane = tid & 31;
    __shared__ float sm[8];
    float4 v = ((float4*)Ar)[tid];
    float m = fmaxf(fmaxf(v.x, v.y), fmaxf(v.z, v.w));
    m = warp_max(m);
    if (lane == 0) sm[wid] = m;
    __syncthreads();
    if (wid == 0) {
        float t = (lane < 8) ? sm[lane] : -3.4e38f;
        t = warp_max(t);
        if (lane == 0) sm[0] = t;
    }
    __syncthreads();
    m = sm[0];
    __syncthreads();
    float e0 = __expf(v.x-m), e1 = __expf(v.y-m), e2 = __expf(v.z-m), e3 = __expf(v.w-m);
    float s = e0+e1+e2+e3;
    s = warp_sum(s);
    if (lane == 0) sm[wid] = s;
    __syncthreads();
    if (wid == 0) {
        float t = (lane < 8) ? sm[lane] : 0.f;
        t = warp_sum(t);
        if (lane == 0) sm[0] = t;
    }
    __syncthreads();
    float inv = 1.f / sm[0];
    float4 o = make_float4(e0*inv, e1*inv, e2*inv, e3*inv);
    ((float4*)Ar)[tid] = o;
    __nv_bfloat162 h0 = __floats2bfloat162_rn(o.x, o.y);
    __nv_bfloat162 h1 = __floats2bfloat162_rn(o.z, o.w);
    ((__nv_bfloat162*)Ah)[tid*2]   = h0;
    ((__nv_bfloat162*)Ah)[tid*2+1] = h1;
}

// ---------------- 5b) transpose: g_Th = (g_Ah)^T per batch (bf16 in/out) ----------------
__global__ __launch_bounds__(256) void transpose_kernel()
{
    __shared__ __nv_bfloat16 t[32][34];
    int b = blockIdx.z;
    int x0 = blockIdx.x*32, y0 = blockIdx.y*32;
    const __nv_bfloat16* Ab = g_Ah + (size_t)b*SS*SS;
    __nv_bfloat16* Tb = g_Th + (size_t)b*SS*SS;
    int tx = threadIdx.x & 31, ty = threadIdx.x >> 5;   // 32 x 8
    #pragma unroll
    for (int i = 0; i < 32; i += 8)
        t[ty+i][tx] = Ab[(size_t)(y0+ty+i)*SS + x0+tx];
    __syncthreads();
    #pragma unroll
    for (int i = 0; i < 32; i += 8)
        Tb[(size_t)(x0+ty+i)*SS + y0+tx] = t[tx][ty+i];
}

// ================= bf16 mma.sync batched NT GEMM =================
// (+rowsum epilogue, + in-epilogue mirror for symmetric tri products)
__device__ __forceinline__ uint32_t s2u(const void* p) {
    uint32_t a;
    asm("{ .reg .u64 t; cvta.to.shared.u64 t, %1; cvt.u32.u64 %0, t; }" : "=r"(a) : "l"(p));
    return a;
}
#define SWZ(o) ((o) ^ (((o)>>3)&0x70))

__device__ __forceinline__ void cp16(uint32_t dst, const void* src) {
    asm volatile("cp.async.cg.shared.global [%0], [%1], 16;" :: "r"(dst), "l"(src));
}
__device__ __forceinline__ void cp_commit() { asm volatile("cp.async.commit_group;" ::: "memory"); }
#define CP_WAIT(n) asm volatile("cp.async.wait_group %0;" :: "n"(n) : "memory")

__device__ __forceinline__ void ldsm4(uint32_t* r, uint32_t addr) {
    asm volatile("ldmatrix.sync.aligned.m8n8.x4.shared.b16 {%0,%1,%2,%3}, [%4];"
        : "=r"(r[0]), "=r"(r[1]), "=r"(r[2]), "=r"(r[3]) : "r"(addr));
}
__device__ __forceinline__ void mma_bf16(float* c, const uint32_t* a,
                                         uint32_t b0, uint32_t b1) {
    asm volatile(
        "mma.sync.aligned.m16n8k16.row.col.f32.bf16.bf16.f32 "
        "{%0,%1,%2,%3},{%4,%5,%6,%7},{%8,%9},{%0,%1,%2,%3};"
        : "+f"(c[0]), "+f"(c[1]), "+f"(c[2]), "+f"(c[3])
        : "r"(a[0]), "r"(a[1]), "r"(a[2]), "r"(a[3]), "r"(b0), "r"(b1));
}

#define STG 3
#define CK 64                        // k per chunk (bf16): 128B per row
#define NCH (SS/CK)                  // 16
#define STAGE_BYTES 32768
#define GEMM_DSMEM (STG*STAGE_BYTES) // 98304

__global__ __launch_bounds__(256, 2)
void gemm_bf16_kernel(int asel, int bsel, int cfsel, int chsel, int tri)
{
    extern __shared__ __align__(16) char dsmem[];
    uint32_t sb = s2u(dsmem);
    int tid = threadIdx.x;
    int warp = tid >> 5, lane = tid & 31;

    size_t off = (size_t)blockIdx.z*SS*SS;
    const __nv_bfloat16* Ag = hmatsel(asel) + off;
    const __nv_bfloat16* Bg = hmatsel(bsel) + off;
    float* Cg = matsel(cfsel) + off;
    __nv_bfloat16* Chg = (chsel >= 0) ? hmatsel(chsel) + off : nullptr;

    int bi, bj;
    if (tri) {
        int t = blockIdx.x, i = 0;
        while (t >= 8 - i) { t -= 8 - i; i++; }
        bi = i; bj = i + t;
    } else {
        bi = blockIdx.x >> 3; bj = blockIdx.x & 7;
    }
    int m0 = bi*128, n0 = bj*128;
    bool same = (tri != 0) && (bi == bj) && (asel == bsel);
    uint32_t bBase = same ? 0u : 16384u;

    int wm = (warp >> 2)*64, wn = (warp & 3)*32;
    int rlane = (lane & 7) + ((lane >> 3) & 1)*8;
    int clane = (lane >> 4) & 1;

    float acc[4][4][4];
    #pragma unroll
    for (int i = 0; i < 4; i++)
        #pragma unroll
        for (int j = 0; j < 4; j++) {
            acc[i][j][0]=0; acc[i][j][1]=0; acc[i][j][2]=0; acc[i][j][3]=0;
        }

    auto load_chunk = [&](int c) {
        uint32_t stg = sb + (uint32_t)(c % STG) * STAGE_BYTES;
        int k0 = c * CK;
        #pragma unroll
        for (int it = 0; it < 8; it++) {
            int u = tid + it*256;
            int r = u >> 3;
            int ch = u & 7;
            if (r < 128) {
                const __nv_bfloat16* gsrc = Ag + (size_t)(m0 + r)*SS + k0 + ch*8;
                cp16(stg + SWZ((uint32_t)(r*128 + ch*16)), gsrc);
            } else if (!same) {
                const __nv_bfloat16* gsrc = Bg + (size_t)(n0 + (r-128))*SS + k0 + ch*8;
                cp16(stg + 16384u + SWZ((uint32_t)((r-128)*128 + ch*16)), gsrc);
            }
        }
    };

    for (int c = 0; c < STG-1; c++) { load_chunk(c); cp_commit(); }

    for (int c = 0; c < NCH; c++) {
        int lc = c + STG - 1;
        if (lc < NCH) load_chunk(lc);
        cp_commit();
        CP_WAIT(STG-1);
        __syncthreads();
        uint32_t stg = sb + (uint32_t)(c % STG) * STAGE_BYTES;
        #pragma unroll
        for (int ks = 0; ks < CK/16; ks++) {
            uint32_t af[4][4], bfr[2][4];
            int kch = ks*2 + clane;
            #pragma unroll
            for (int mi = 0; mi < 4; mi++) {
                int r = wm + mi*16 + rlane;
                ldsm4(af[mi], stg + SWZ((uint32_t)(r*128 + kch*16)));
            }
            #pragma unroll
            for (int nt = 0; nt < 2; nt++) {
                int r = wn + nt*16 + rlane;
                ldsm4(bfr[nt], stg + bBase + SWZ((uint32_t)(r*128 + kch*16)));
            }
            #pragma unroll
            for (int mi = 0; mi < 4; mi++)
                #pragma unroll
                for (int nj = 0; nj < 4; nj++) {
                    int nt = nj >> 1, sel = nj & 1;
                    mma_bf16(acc[mi][nj], af[mi], bfr[nt][sel], bfr[nt][sel+2]);
                }
        }
        __syncthreads();
    }

    int rr = lane >> 2, cc2 = (lane & 3)*2;
    #pragma unroll
    for (int mi = 0; mi < 4; mi++) {
        #pragma unroll
        for (int nj = 0; nj < 4; nj++) {
            int row = m0 + wm + mi*16 + rr;
            int col = n0 + wn + nj*8 + cc2;
            float2 v01 = make_float2(acc[mi][nj][0], acc[mi][nj][1]);
            float2 v23 = make_float2(acc[mi][nj][2], acc[mi][nj][3]);
            *(float2*)&Cg[(size_t)row*SS + col]     = v01;
            *(float2*)&Cg[(size_t)(row+8)*SS + col] = v23;
            if (Chg) {
                *(__nv_bfloat162*)&Chg[(size_t)row*SS + col] =
                    __floats2bfloat162_rn(v01.x, v01.y);
                *(__nv_bfloat162*)&Chg[(size_t)(row+8)*SS + col] =
                    __floats2bfloat162_rn(v23.x, v23.y);
            }
        }
    }

    // ---- rowsum epilogue: slot index == cfsel ----
    float* rs = g_rs + (size_t)cfsel*NTOK + (size_t)blockIdx.z*SS;
    #pragma unroll
    for (int mi = 0; mi < 4; mi++) {
        float r0 = 0.f, r1 = 0.f;
        #pragma unroll
        for (int nj = 0; nj < 4; nj++) {
            r0 += acc[mi][nj][0] + acc[mi][nj][1];
            r1 += acc[mi][nj][2] + acc[mi][nj][3];
        }
        r0 += __shfl_xor_sync(0xffffffffu, r0, 1);
        r0 += __shfl_xor_sync(0xffffffffu, r0, 2);
        r1 += __shfl_xor_sync(0xffffffffu, r1, 1);
        r1 += __shfl_xor_sync(0xffffffffu, r1, 2);
        if ((lane & 3) == 0) {
            int row = m0 + wm + mi*16 + rr;
            atomicAdd(&rs[row], r0);
            atomicAdd(&rs[row+8], r1);
        }
    }
    if (tri && bi != bj) {
        #pragma unroll
        for (int nj = 0; nj < 4; nj++) {
            float c0 = 0.f, c1 = 0.f;
            #pragma unroll
            for (int mi = 0; mi < 4; mi++) {
                c0 += acc[mi][nj][0] + acc[mi][nj][2];
                c1 += acc[mi][nj][1] + acc[mi][nj][3];
            }
            c0 += __shfl_xor_sync(0xffffffffu, c0, 4);
            c0 += __shfl_xor_sync(0xffffffffu, c0, 8);
            c0 += __shfl_xor_sync(0xffffffffu, c0, 16);
            c1 += __shfl_xor_sync(0xffffffffu, c1, 4);
            c1 += __shfl_xor_sync(0xffffffffu, c1, 8);
            c1 += __shfl_xor_sync(0xffffffffu, c1, 16);
            if (lane < 4) {
                int col = n0 + wn + nj*8 + cc2;
                atomicAdd(&rs[col], c0);
                atomicAdd(&rs[col+1], c1);
            }
        }

        // ---- in-epilogue mirror: write transposed tile (lower triangle) ----
        // smem is free after the mainloop's trailing __syncthreads.
        float (*tileT)[133] = (float (*)[133])dsmem;   // [col][row], pad 133
        #pragma unroll
        for (int mi = 0; mi < 4; mi++)
            #pragma unroll
            for (int nj = 0; nj < 4; nj++) {
                int rowL = wm + mi*16 + rr;
                int colL = wn + nj*8 + cc2;
                tileT[colL  ][rowL  ] = acc[mi][nj][0];
                tileT[colL+1][rowL  ] = acc[mi][nj][1];
                tileT[colL  ][rowL+8] = acc[mi][nj][2];
                tileT[colL+1][rowL+8] = acc[mi][nj][3];
            }
        __syncthreads();
        #pragma unroll
        for (int it = 0; it < 16; it++) {
            int idx = tid + it*256;          // 0..4095
            int cl = idx >> 5;               // 0..127  (local col = global row of C^T)
            int f4 = (idx & 31)*4;           // 0..124
            float4 v = make_float4(tileT[cl][f4], tileT[cl][f4+1],
                                   tileT[cl][f4+2], tileT[cl][f4+3]);
            *(float4*)&Cg[(size_t)(n0 + cl)*SS + m0 + f4] = v;
            if (Chg) {
                *(__nv_bfloat162*)&Chg[(size_t)(n0 + cl)*SS + m0 + f4] =
                    __floats2bfloat162_rn(v.x, v.y);
                *(__nv_bfloat162*)&Chg[(size_t)(n0 + cl)*SS + m0 + f4 + 2] =
                    __floats2bfloat162_rn(v.z, v.w);
            }
        }
    }
}

// ---------------- 8a) fused matrices: single pass, batched reciprocal ----------------
__device__ __forceinline__ void fuse_nd(float a, float b, float c,
                                        float ia, float ib, float ic,
                                        float& num, float& d)
{
    float ps = fminf(fmaxf(a*ia, EPSV), 1.f-EPSV);
    float pc = fminf(fmaxf(b*ib, EPSV), 1.f-EPSV);
    float pp = fminf(fmaxf(c*ic, EPSV), 1.f-EPSV);
    num = ps*pc*pp;
    float den = (1.f-ps+EPSV)*(1.f-pc+EPSV)*(1.f-pp+EPSV);
    d = num + den;
}
__device__ __forceinline__ float fuse1_gen(float a, float b, float c,
                                           float ia, float ib, float ic,
                                           float w0, float w1, float w2, float fb)
{
    float ps = fminf(fmaxf(a*ia, EPSV), 1.f-EPSV);
    float pc = fminf(fmaxf(b*ib, EPSV), 1.f-EPSV);
    float pp = fminf(fmaxf(c*ic, EPSV), 1.f-EPSV);
    float L0 = __logf(__fdividef(ps, 1.f-ps+EPSV));
    float L1 = __logf(__fdividef(pc, 1.f-pc+EPSV));
    float L2 = __logf(__fdividef(pp, 1.f-pp+EPSV));
    float logit = fb + w0*L0 + w1*L1 + w2*L2;
    return __fdividef(1.f, 1.f+__expf(-logit));
}

__global__ __launch_bounds__(256) void fusedmat_kernel(
    const float* __restrict__ fusion_w, const float* __restrict__ fusion_b)
{
    __shared__ float irs_s[16], irs_c[16], irs_p[16];
    int hop = blockIdx.z, b = blockIdx.y, sr0 = blockIdx.x*16;
    int tid = threadIdx.x;
    const float *Ms, *Mc, *Mp;
    if (hop == 0) { Ms = g_A;  Mc = g_P;  Mp = g_Qm; }
    else          { Ms = g_A2; Mc = g_P2; Mp = g_Q2; }
    float w0 = fusion_w[hop*3+0], w1 = fusion_w[hop*3+1], w2 = fusion_w[hop*3+2];
    float fb = fusion_b[hop];
    bool unitw = (w0 == 1.f) && (w1 == 1.f) && (w2 == 1.f) && (fb == 0.f);
    size_t rowbase = (size_t)b*SS + sr0;

    if (tid < 16) {
        if (hop == 0) irs_s[tid] = 1.f/(1.f + EPSV);   // softmax rows sum to 1
        else irs_s[tid] = 1.f/(g_rs[(size_t)3*NTOK + rowbase + tid] + EPSV);
        irs_c[tid] = 1.f/(g_rs[(size_t)(hop ? 4 : 1)*NTOK + rowbase + tid] + EPSV);
        irs_p[tid] = 1.f/(g_rs[(size_t)(hop ? 5 : 2)*NTOK + rowbase + tid] + EPSV);
    }
    __syncthreads();

    int r = tid >> 4, c16 = tid & 15;
    float ia = irs_s[r], ib = irs_c[r], ic = irs_p[r];
    size_t rowoff = (rowbase + r)*SS;
    float* Fr = g_F + (size_t)hop*NB*SS*SS + rowoff;
    float sum = 0.f;
    #pragma unroll
    for (int j = 0; j < 16; j++) {
        int col = c16*4 + j*64;
        float4 ms = *(const float4*)(Ms + rowoff + col);
        float4 mc = *(const float4*)(Mc + rowoff + col);
        float4 mp = *(const float4*)(Mp + rowoff + col);
        float4 f;
        if (unitw) {
            float n0, n1, n2, n3, d0, d1, d2, d3;
            fuse_nd(ms.x, mc.x, mp.x, ia, ib, ic, n0, d0);
            fuse_nd(ms.y, mc.y, mp.y, ia, ib, ic, n1, d1);
            fuse_nd(ms.z, mc.z, mp.z, ia, ib, ic, n2, d2);
            fuse_nd(ms.w, mc.w, mp.w, ia, ib, ic, n3, d3);
            float t01 = d0*d1, t23 = d2*d3;
            float rD = __fdividef(1.f, t01*t23);   // single MUFU for 4 divisions
            f.x = n0 * (d1*t23*rD);
            f.y = n1 * (d0*t23*rD);
            f.z = n2 * (t01*d3*rD);
            f.w = n3 * (t01*d2*rD);
        } else {
            f.x = fuse1_gen(ms.x, mc.x, mp.x, ia, ib, ic, w0, w1, w2, fb);
            f.y = fuse1_gen(ms.y, mc.y, mp.y, ia, ib, ic, w0, w1, w2, fb);
            f.z = fuse1_gen(ms.z, mc.z, mp.z, ia, ib, ic, w0, w1, w2, fb);
            f.w = fuse1_gen(ms.w, mc.w, mp.w, ia, ib, ic, w0, w1, w2, fb);
        }
        sum += (f.x+f.y) + (f.z+f.w);
        *(float4*)(Fr + col) = f;
    }
    #pragma unroll
    for (int o = 8; o > 0; o >>= 1) sum += __shfl_xor_sync(0xffffffffu, sum, o);
    if (c16 == 0) g_frs[(size_t)hop*NTOK + rowbase + r] = sum;
}

// ---------------- 8b) H[hop] += F @ hopvT^T  (TF32 mma, split-K x4) ----------------
__device__ __forceinline__ float to_tf32(float x) {
    uint32_t u;
    asm("cvt.rna.tf32.f32 %0, %1;" : "=r"(u) : "f"(x));
    return __uint_as_float(u);
}
__device__ __forceinline__ void mma_tf32(float* c,
    uint32_t a0, uint32_t a1, uint32_t a2, uint32_t a3, uint32_t b0, uint32_t b1)
{
    asm volatile(
        "mma.sync.aligned.m16n8k8.row.col.f32.tf32.tf32.f32 "
        "{%0,%1,%2,%3},{%4,%5,%6,%7},{%8,%9},{%0,%1,%2,%3};"
        : "+f"(c[0]), "+f"(c[1]), "+f"(c[2]), "+f"(c[3])
        : "r"(a0), "r"(a1), "r"(a2), "r"(a3), "r"(b0), "r"(b1));
}

#define HKS 4                     // split-K factor
#define HKC (SS/HKS)              // 256 k per block

__global__ __launch_bounds__(256) void hop_gemm_kernel()
{
    __shared__ float As[16][132];   // [k][m]
    __shared__ float Bs[16][68];    // [k][n]
    int tid = threadIdx.x;
    int warp = tid >> 5, lane = tid & 31;
    int hop = blockIdx.z >> 2, kc = blockIdx.z & 3;
    int b = blockIdx.y, m0 = blockIdx.x*128;

    const float* Ag = g_F + (size_t)hop*NB*SS*SS + (size_t)b*SS*SS;
    const float* Bg = g_hopvT + (size_t)(hop*NB + b)*DD*SS;
    float* Hg = g_H + (size_t)hop*NTOK*DD + (size_t)b*SS*DD;

    int wr = warp >> 1, wc = warp & 1;     // 4 x 2 warps, tile 32(m) x 32(n)
    int group = lane >> 2, tig = lane & 3;

    float acc[2][4][4];
    #pragma unroll
    for (int i = 0; i < 2; i++)
        #pragma unroll
        for (int j = 0; j < 4; j++) {
            acc[i][j][0]=0; acc[i][j][1]=0; acc[i][j][2]=0; acc[i][j][3]=0;
        }

    int kk = tid & 15, msi = tid >> 4;     // staging indices
    for (int k0 = kc*HKC; k0 < kc*HKC + HKC; k0 += 16) {
        #pragma unroll
        for (int p = 0; p < 8; p++)
            As[kk][msi + p*16] = to_tf32(Ag[(size_t)(m0 + msi + p*16)*SS + k0 + kk]);
        #pragma unroll
        for (int p = 0; p < 4; p++)
            Bs[kk][msi + p*16] = to_tf32(Bg[(size_t)(msi + p*16)*SS + k0 + kk]);
        __syncthreads();
        #pragma unroll
        for (int ks = 0; ks < 2; ks++) {
            int kb = ks * 8;
            uint32_t af[2][4], bf[4][2];
            #pragma unroll
            for (int mi = 0; mi < 2; mi++) {
                int mb = wr*32 + mi*16 + group;
                af[mi][0] = __float_as_uint(As[kb+tig  ][mb]);
                af[mi][1] = __float_as_uint(As[kb+tig  ][mb+8]);
                af[mi][2] = __float_as_uint(As[kb+tig+4][mb]);
                af[mi][3] = __float_as_uint(As[kb+tig+4][mb+8]);
            }
            #pragma unroll
            for (int nj = 0; nj < 4; nj++) {
                int nb = wc*32 + nj*8 + group;
                bf[nj][0] = __float_as_uint(Bs[kb+tig  ][nb]);
                bf[nj][1] = __float_as_uint(Bs[kb+tig+4][nb]);
            }
            #pragma unroll
            for (int mi = 0; mi < 2; mi++)
                #pragma unroll
                for (int nj = 0; nj < 4; nj++)
                    mma_tf32(acc[mi][nj], af[mi][0], af[mi][1], af[mi][2], af[mi][3],
                             bf[nj][0], bf[nj][1]);
        }
        __syncthreads();
    }

    #pragma unroll
    for (int mi = 0; mi < 2; mi++)
        #pragma unroll
        for (int nj = 0; nj < 4; nj++) {
            int row = m0 + wr*32 + mi*16 + group;
            int col = wc*32 + nj*8 + 2*tig;
            atomicAdd(&Hg[(size_t)row*DD + col],     acc[mi][nj][0]);
            atomicAdd(&Hg[(size_t)row*DD + col + 1], acc[mi][nj][1]);
            atomicAdd(&Hg[(size_t)(row+8)*DD + col],     acc[mi][nj][2]);
            atomicAdd(&Hg[(size_t)(row+8)*DD + col + 1], acc[mi][nj][3]);
        }
}

// ---------------- 9) out = (gate-combined H) @ out_W^T ----------------
__global__ __launch_bounds__(256) void outproj_kernel(
    const float* __restrict__ outW, float* __restrict__ out)
{
    __shared__ float cs[16][65];
    __shared__ float ws[128][65];
    int tb = blockIdx.x * 16;
    int tid = threadIdx.x;
    #pragma unroll
    for (int e = tid; e < 16*64; e += 256) {
        int tl = e >> 6, ee = e & 63;
        int tok = tb + tl;
        float s0 = __fdividef(g_gate[tok*2+0], g_frs[tok] + EPSV);
        float s1 = __fdividef(g_gate[tok*2+1], g_frs[NTOK + tok] + EPSV);
        cs[tl][ee] = s0*g_H[(size_t)tok*DD + ee]
                   + s1*g_H[(size_t)NTOK*DD + (size_t)tok*DD + ee];
    }
    int tk2 = tid >> 5;
    int h4  = tid & 31;
    for (int hc = 0; hc < 4; hc++) {
        __syncthreads();
        #pragma unroll
        for (int e = tid; e < 128*64; e += 256)
            ws[e>>6][e&63] = outW[(size_t)hc*128*DD + e];
        __syncthreads();
        float a0[4] = {0,0,0,0}, a1[4] = {0,0,0,0};
        #pragma unroll 4
        for (int d = 0; d < 64; d++) {
            float c0 = cs[2*tk2][d], c1 = cs[2*tk2+1][d];
            #pragma unroll
            for (int j = 0; j < 4; j++) {
                float w = ws[h4*4 + j][d];
                a0[j] += c0*w; a1[j] += c1*w;
            }
        }
        *(float4*)&out[(size_t)(tb + 2*tk2)*HID + hc*128 + h4*4] =
            make_float4(a0[0], a0[1], a0[2], a0[3]);
        *(float4*)&out[(size_t)(tb + 2*tk2 + 1)*HID + hc*128 + h4*4] =
            make_float4(a1[0], a1[1], a1[2], a1[3]);
    }
}

// ---------------- launch ----------------
extern "C" void kernel_launch(void* const* d_in, const int* in_sizes, int n_in,
                              void* d_out, int out_size)
{
    const float* x      = (const float*)d_in[0];
    const float* Wq     = (const float*)d_in[1];
    const float* Wk     = (const float*)d_in[2];
    const float* Wv     = (const float*)d_in[3];
    const float* btab   = (const float*)d_in[4];
    const float* fw     = (const float*)d_in[5];
    const float* fbias  = (const float*)d_in[6];
    const float* hopW   = (const float*)d_in[7];
    const float* gateW  = (const float*)d_in[8];
    const float* gateb  = (const float*)d_in[9];
    const float* outW   = (const float*)d_in[10];
    const float* temp   = (const float*)d_in[11];
    const int*   relidx = (const int*)d_in[12];
    float* out = (float*)d_out;

    cudaFuncSetAttribute(gemm_bf16_kernel,
                         cudaFuncAttributeMaxDynamicSharedMemorySize, GEMM_DSMEM);

    zero_kernel<<<ZERO_BLOCKS, 256>>>();
    proj_kernel<<<NTOK/TOK_PB, 256>>>(x, Wq, Wk, Wv, gateW);
    rope_kernel<<<(NTOK*32)/256, 256>>>();
    hopv_gate_kernel<<<dim3(NTOK/64, 4), 256>>>(hopW, gateb);
    scores_kernel<<<dim3(16,16,NB), 256>>>(btab, relidx, temp);
    softmax_kernel<<<NTOK, 256>>>();
    transpose_kernel<<<dim3(32,32,NB), 256>>>();

    // hmat: 0=Ah 1=Th 2=Ph 3=Qmh ; mat: 1=P 2=Qm 3=A2 4=P2 5=Q2
    // tri GEMMs mirror their own lower triangle in the epilogue now.
    gemm_bf16_kernel<<<dim3(36,1,NB), 256, GEMM_DSMEM>>>(0,0,1, 2, 1); // P  = Ah Ah^T (tri)
    gemm_bf16_kernel<<<dim3(36,1,NB), 256, GEMM_DSMEM>>>(1,1,2, 3, 1); // Qm = Th Th^T (tri)
    gemm_bf16_kernel<<<dim3(64,1,NB), 256, GEMM_DSMEM>>>(0,1,3,-1, 0); // A2 = Ah Th^T (full)
    gemm_bf16_kernel<<<dim3(36,1,NB), 256, GEMM_DSMEM>>>(2,2,4,-1, 1); // P2 = Ph Ph^T (tri)
    gemm_bf16_kernel<<<dim3(36,1,NB), 256, GEMM_DSMEM>>>(3,3,5,-1, 1); // Q2 = Qmh Qmh^T (tri)

    fusedmat_kernel<<<dim3(SS/16, NB, 2), 256>>>(fw, fbias);
    hop_gemm_kernel<<<dim3(8, NB, HKS*2), 256>>>();
    outproj_kernel<<<NTOK/16, 256>>>(outW, out);
}